// round 4
// baseline (speedup 1.0000x reference)
#include <cuda_runtime.h>
#include <cuda_bf16.h>
#include <math.h>

#define N_NODES 100000
#define N_EDGES 1600000
#define IN_DIM  500
#define HID_DIM 128
#define OUT_DIM 40

// ---------------- scratch (device globals; no allocation allowed) ----------------
__device__ int   g_is64;                 // 1 if edge_index is int64, 0 if int32
__device__ __align__(256) int   g_deg[N_NODES];
__device__ __align__(256) int   g_cursor[N_NODES];
__device__ __align__(256) float g_dinv[N_NODES];
__device__ __align__(256) int   g_rowptr[N_NODES + 1];
__device__ __align__(256) int   g_csr_src[N_EDGES];
__device__ __align__(256) float g_csr_w[N_EDGES];
__device__ __align__(256) float g_h1[(size_t)N_NODES * HID_DIM];   // x@W1
__device__ __align__(256) float g_a1[(size_t)N_NODES * HID_DIM];   // relu(agg1 + b1)
__device__ __align__(256) float g_h2[(size_t)N_NODES * OUT_DIM];   // a1@W2

// ---------------- edge decode helpers ----------------
__device__ __forceinline__ int edge_id(const void* ei, size_t idx) {
    if (g_is64) return (int)((const long long*)ei)[idx];
    return ((const int*)ei)[idx];
}

// Detect edge_index dtype: int64 node ids are all in [0, N_NODES);
// int32 data read as int64 fuses adjacent ids -> values >= 2^32 (or negative).
__global__ void k_detect(const void* ei) {
    const long long* p = (const long long*)ei;
    int is64 = 1;
    for (int i = 0; i < 16; i++) {
        long long v = p[i];
        if (v < 0 || v >= N_NODES) { is64 = 0; break; }
    }
    g_is64 = is64;
}

// ---------------- preprocessing ----------------
__global__ void k_init() {
    int i = blockIdx.x * 256 + threadIdx.x;
    if (i < N_NODES) { g_deg[i] = 0; g_cursor[i] = 0; }
}

__global__ void k_degree(const void* __restrict__ ei) {
    int e = blockIdx.x * 256 + threadIdx.x;
    if (e >= N_EDGES) return;
    int d = edge_id(ei, (size_t)N_EDGES + e);
    if ((unsigned)d < N_NODES) atomicAdd(&g_deg[d], 1);
}

__global__ void k_dinv() {
    int i = blockIdx.x * 256 + threadIdx.x;
    if (i < N_NODES) g_dinv[i] = rsqrtf((float)(g_deg[i] + 1));  // +1 self loop
}

// single-block chunked exclusive scan of g_deg -> g_rowptr
__global__ void k_scan() {
    __shared__ int wsum[32];
    __shared__ int carry_sh;
    int t = threadIdx.x;
    int lane = t & 31, wid = t >> 5;
    if (t == 0) carry_sh = 0;
    __syncthreads();
    for (int base = 0; base < N_NODES; base += 1024) {
        int idx = base + t;
        int v = (idx < N_NODES) ? g_deg[idx] : 0;
        int x = v;
        #pragma unroll
        for (int d = 1; d < 32; d <<= 1) {
            int y = __shfl_up_sync(0xffffffffu, x, d);
            if (lane >= d) x += y;
        }
        if (lane == 31) wsum[wid] = x;
        __syncthreads();
        if (wid == 0) {
            int s = wsum[lane];
            #pragma unroll
            for (int d = 1; d < 32; d <<= 1) {
                int y = __shfl_up_sync(0xffffffffu, s, d);
                if (lane >= d) s += y;
            }
            wsum[lane] = s;
        }
        __syncthreads();
        int woff = (wid > 0) ? wsum[wid - 1] : 0;
        int excl = carry_sh + woff + (x - v);
        if (idx < N_NODES) g_rowptr[idx] = excl;
        __syncthreads();
        if (t == 0) carry_sh += wsum[31];
        __syncthreads();
    }
    if (t == 0) g_rowptr[N_NODES] = carry_sh;
}

__global__ void k_scatter(const void* __restrict__ ei) {
    int e = blockIdx.x * 256 + threadIdx.x;
    if (e >= N_EDGES) return;
    int s = edge_id(ei, e);
    int d = edge_id(ei, (size_t)N_EDGES + e);
    if ((unsigned)s >= N_NODES || (unsigned)d >= N_NODES) return;
    int p = g_rowptr[d] + atomicAdd(&g_cursor[d], 1);
    g_csr_src[p] = s;
    g_csr_w[p]   = g_dinv[s] * g_dinv[d];
}

// ---------------- GEMM1: g_h1 = x @ W1   (100000x500 @ 500x128) ----------------
// 64x128 block tile, KC=20, 256 threads, 8x4 outputs/thread.
__global__ __launch_bounds__(256) void k_gemm1(const float* __restrict__ X,
                                               const float* __restrict__ W) {
    __shared__ float As[20][65];   // [k][m], padded
    __shared__ float Bs[20][128];  // [k][n]
    int t = threadIdx.x;
    int tx = t & 31;       // col group: cols tx*4..+3
    int ty = t >> 5;       // row group: rows ty*8..+7
    int row0 = blockIdx.x * 64;

    float acc[8][4];
    #pragma unroll
    for (int i = 0; i < 8; i++)
        #pragma unroll
        for (int j = 0; j < 4; j++) acc[i][j] = 0.f;

    for (int kt = 0; kt < IN_DIM; kt += 20) {
        #pragma unroll
        for (int j = 0; j < 5; j++) {              // A: 64x20 = 1280 elems
            int i = t + j * 256;
            int r = i / 20, kk = i % 20;
            int gr = row0 + r;
            As[kk][r] = (gr < N_NODES) ? X[(size_t)gr * IN_DIM + kt + kk] : 0.f;
        }
        #pragma unroll
        for (int j = 0; j < 10; j++) {             // B: 20x128 = 2560 elems
            int i = t + j * 256;
            int n = i & 127, kk = i >> 7;
            Bs[kk][n] = W[(size_t)(kt + kk) * HID_DIM + n];
        }
        __syncthreads();
        #pragma unroll
        for (int k = 0; k < 20; k++) {
            float4 b4 = *(const float4*)&Bs[k][tx * 4];
            #pragma unroll
            for (int i = 0; i < 8; i++) {
                float a = As[k][ty * 8 + i];
                acc[i][0] += a * b4.x;
                acc[i][1] += a * b4.y;
                acc[i][2] += a * b4.z;
                acc[i][3] += a * b4.w;
            }
        }
        __syncthreads();
    }
    #pragma unroll
    for (int i = 0; i < 8; i++) {
        int gr = row0 + ty * 8 + i;
        if (gr < N_NODES) {
            float4 v = make_float4(acc[i][0], acc[i][1], acc[i][2], acc[i][3]);
            *(float4*)&g_h1[(size_t)gr * HID_DIM + tx * 4] = v;
        }
    }
}

// ---------------- aggregation 1: warp per node, reads CSR, relu(agg+b1) ----------------
__global__ __launch_bounds__(256) void k_agg1(const float* __restrict__ b1) {
    int node = blockIdx.x * 8 + (threadIdx.x >> 5);
    if (node >= N_NODES) return;
    int lane = threadIdx.x & 31;
    const float4* h = (const float4*)g_h1;

    float di = g_dinv[node];
    float ws = di * di;                 // self-loop weight
    float4 acc = h[(size_t)node * 32 + lane];
    acc.x *= ws; acc.y *= ws; acc.z *= ws; acc.w *= ws;

    int p0 = g_rowptr[node], p1 = g_rowptr[node + 1];
    for (int p = p0; p < p1; p++) {
        int s  = g_csr_src[p];
        float w = g_csr_w[p];
        float4 v = h[(size_t)s * 32 + lane];
        acc.x += w * v.x; acc.y += w * v.y; acc.z += w * v.z; acc.w += w * v.w;
    }
    float4 bb = ((const float4*)b1)[lane];
    float4 o;
    o.x = fmaxf(acc.x + bb.x, 0.f);
    o.y = fmaxf(acc.y + bb.y, 0.f);
    o.z = fmaxf(acc.z + bb.z, 0.f);
    o.w = fmaxf(acc.w + bb.w, 0.f);
    ((float4*)g_a1)[(size_t)node * 32 + lane] = o;
}

// ---------------- GEMM2: g_h2 = g_a1 @ W2  (100000x128 @ 128x40) ----------------
__global__ __launch_bounds__(256) void k_gemm2(const float* __restrict__ W2) {
    __shared__ float Hs[32][129];
    __shared__ float Ws[128][40];
    int t = threadIdx.x;
    int row0 = blockIdx.x * 32;

    #pragma unroll
    for (int j = 0; j < 20; j++) {                 // 128x40 = 5120
        int i = t + j * 256;
        Ws[i / 40][i % 40] = W2[i];
    }
    #pragma unroll
    for (int j = 0; j < 16; j++) {                 // 32x128 = 4096
        int i = t + j * 256;
        int r = i >> 7, c = i & 127;
        int gr = row0 + r;
        Hs[r][c] = (gr < N_NODES) ? g_a1[(size_t)gr * HID_DIM + c] : 0.f;
    }
    __syncthreads();

    int r = t >> 3;
    int c0 = (t & 7) * 5;
    float acc[5] = {0.f, 0.f, 0.f, 0.f, 0.f};
    #pragma unroll 8
    for (int k = 0; k < 128; k++) {
        float a = Hs[r][k];
        #pragma unroll
        for (int j = 0; j < 5; j++) acc[j] += a * Ws[k][c0 + j];
    }
    int gr = row0 + r;
    if (gr < N_NODES) {
        #pragma unroll
        for (int j = 0; j < 5; j++)
            g_h2[(size_t)gr * OUT_DIM + c0 + j] = acc[j];
    }
}

// ---------------- aggregation 2 + bias + log_softmax: warp per node ----------------
__global__ __launch_bounds__(256) void k_agg2(const float* __restrict__ b2,
                                              float* __restrict__ out) {
    int node = blockIdx.x * 8 + (threadIdx.x >> 5);
    if (node >= N_NODES) return;
    int lane = threadIdx.x & 31;

    float di = g_dinv[node];
    float ws = di * di;
    float acc0, acc1 = 0.f;
    {
        size_t b = (size_t)node * OUT_DIM;
        acc0 = ws * g_h2[b + lane];
        if (lane < 8) acc1 = ws * g_h2[b + 32 + lane];
    }
    int p0 = g_rowptr[node], p1 = g_rowptr[node + 1];
    for (int p = p0; p < p1; p++) {
        int s  = g_csr_src[p];
        float w = g_csr_w[p];
        size_t b = (size_t)s * OUT_DIM;
        acc0 += w * g_h2[b + lane];
        if (lane < 8) acc1 += w * g_h2[b + 32 + lane];
    }
    acc0 += b2[lane];
    if (lane < 8) acc1 += b2[32 + lane];

    // log_softmax over 40 values spread across the warp
    float m = acc0;
    if (lane < 8) m = fmaxf(m, acc1);
    #pragma unroll
    for (int o = 16; o; o >>= 1) m = fmaxf(m, __shfl_xor_sync(0xffffffffu, m, o));
    float s = __expf(acc0 - m) + ((lane < 8) ? __expf(acc1 - m) : 0.f);
    #pragma unroll
    for (int o = 16; o; o >>= 1) s += __shfl_xor_sync(0xffffffffu, s, o);
    float ls = __logf(s);

    out[(size_t)node * OUT_DIM + lane] = acc0 - m - ls;
    if (lane < 8) out[(size_t)node * OUT_DIM + 32 + lane] = acc1 - m - ls;
}

// ---------------- launch ----------------
extern "C" void kernel_launch(void* const* d_in, const int* in_sizes, int n_in,
                              void* d_out, int out_size) {
    const float* x  = (const float*)d_in[0];
    const void*  ei = d_in[1];
    const float* W1 = (const float*)d_in[2];
    const float* b1 = (const float*)d_in[3];
    const float* W2 = (const float*)d_in[4];
    const float* b2 = (const float*)d_in[5];
    float*       out = (float*)d_out;

    const int TB = 256;
    int nb_nodes = (N_NODES + TB - 1) / TB;
    int nb_edges = (N_EDGES + TB - 1) / TB;

    k_detect<<<1, 1>>>(ei);
    k_init<<<nb_nodes, TB>>>();
    k_degree<<<nb_edges, TB>>>(ei);
    k_dinv<<<nb_nodes, TB>>>();
    k_scan<<<1, 1024>>>();
    k_scatter<<<nb_edges, TB>>>(ei);

    k_gemm1<<<(N_NODES + 63) / 64, 256>>>(x, W1);
    k_agg1<<<(N_NODES + 7) / 8, 256>>>(b1);
    k_gemm2<<<(N_NODES + 31) / 32, 256>>>(W2);
    k_agg2<<<(N_NODES + 7) / 8, 256>>>(b2, out);
}

// round 9
// speedup vs baseline: 1.1934x; 1.1934x over previous
#include <cuda_runtime.h>
#include <cuda_bf16.h>
#include <mma.h>
#include <math.h>
#include <stdint.h>

using namespace nvcuda;

#define N_NODES 100000
#define N_PAD   100096          // 782 * 128
#define N_EDGES 1600000
#define IN_DIM  500
#define HID_DIM 128
#define OUT_DIM 40
#define K_PAD   512

// ---------------- scratch ----------------
__device__ int   g_is64;
__device__ __align__(256) int   g_deg[N_NODES];
__device__ __align__(256) int   g_cursor[N_NODES];
__device__ __align__(256) float g_dinv[N_NODES];
__device__ __align__(256) int   g_rowptr[N_NODES + 1];
__device__ __align__(256) int   g_bsum[128];
__device__ __align__(256) int   g_csr_src[N_EDGES];
__device__ __align__(256) float g_csr_w[N_EDGES];
__device__ __align__(256) __nv_bfloat16 g_w1hi[K_PAD * HID_DIM];  // [k][n], k padded
__device__ __align__(256) __nv_bfloat16 g_w1lo[K_PAD * HID_DIM];
__device__ __align__(256) float g_h1[(size_t)N_PAD * HID_DIM];
__device__ __align__(256) float g_a1[(size_t)N_PAD * HID_DIM];
__device__ __align__(256) float g_h2[(size_t)N_NODES * OUT_DIM];

// ---------------- edge decode ----------------
__device__ __forceinline__ int edge_id(const void* ei, size_t idx) {
    if (g_is64) return (int)((const long long*)ei)[idx];
    return ((const int*)ei)[idx];
}
__global__ void k_detect(const void* ei) {
    const long long* p = (const long long*)ei;
    int is64 = 1;
    for (int i = 0; i < 16; i++) {
        long long v = p[i];
        if (v < 0 || v >= N_NODES) { is64 = 0; break; }
    }
    g_is64 = is64;
}

// ---------------- preprocessing ----------------
__global__ void k_init() {
    int i = blockIdx.x * 256 + threadIdx.x;
    if (i < N_NODES) { g_deg[i] = 0; g_cursor[i] = 0; }
}
__global__ void k_degree(const void* __restrict__ ei) {
    int e = blockIdx.x * 256 + threadIdx.x;
    if (e >= N_EDGES) return;
    int d = edge_id(ei, (size_t)N_EDGES + e);
    if ((unsigned)d < N_NODES) atomicAdd(&g_deg[d], 1);
}
__global__ void k_dinv() {
    int i = blockIdx.x * 256 + threadIdx.x;
    if (i < N_NODES) g_dinv[i] = rsqrtf((float)(g_deg[i] + 1));
}

// multi-block scan
__global__ __launch_bounds__(1024) void k_scan1() {
    __shared__ int wsum[32];
    int t = threadIdx.x, lane = t & 31, w = t >> 5;
    int idx = blockIdx.x * 1024 + t;
    int v = (idx < N_NODES) ? g_deg[idx] : 0;
    int x = v;
    #pragma unroll
    for (int d = 1; d < 32; d <<= 1) {
        int y = __shfl_up_sync(0xffffffffu, x, d);
        if (lane >= d) x += y;
    }
    if (lane == 31) wsum[w] = x;
    __syncthreads();
    if (w == 0) {
        int s = wsum[lane];
        #pragma unroll
        for (int d = 1; d < 32; d <<= 1) {
            int y = __shfl_up_sync(0xffffffffu, s, d);
            if (lane >= d) s += y;
        }
        wsum[lane] = s;
    }
    __syncthreads();
    int woff = w ? wsum[w - 1] : 0;
    if (idx < N_NODES) g_rowptr[idx] = woff + x - v;
    if (t == 1023) g_bsum[blockIdx.x] = wsum[31];
}
__global__ void k_scan2(int nb) {
    __shared__ int ws[4];
    __shared__ int tot;
    int t = threadIdx.x, lane = t & 31, w = t >> 5;
    int v = (t < nb) ? g_bsum[t] : 0;
    int x = v;
    #pragma unroll
    for (int d = 1; d < 32; d <<= 1) {
        int y = __shfl_up_sync(0xffffffffu, x, d);
        if (lane >= d) x += y;
    }
    if (lane == 31) ws[w] = x;
    __syncthreads();
    if (t == 0) {
        int s = 0;
        #pragma unroll
        for (int i = 0; i < 4; i++) { int tv = ws[i]; ws[i] = s; s += tv; }
        tot = s;
    }
    __syncthreads();
    if (t < nb) g_bsum[t] = ws[w] + x - v;
    if (t == 0) g_rowptr[N_NODES] = tot;
}
__global__ void k_scan3() {
    int idx = blockIdx.x * 256 + threadIdx.x;
    if (idx < N_NODES) g_rowptr[idx] += g_bsum[idx >> 10];
}
__global__ void k_scatter(const void* __restrict__ ei) {
    int e = blockIdx.x * 256 + threadIdx.x;
    if (e >= N_EDGES) return;
    int s = edge_id(ei, e);
    int d = edge_id(ei, (size_t)N_EDGES + e);
    if ((unsigned)s >= N_NODES || (unsigned)d >= N_NODES) return;
    int p = g_rowptr[d] + atomicAdd(&g_cursor[d], 1);
    g_csr_src[p] = s;
    g_csr_w[p]   = g_dinv[s] * g_dinv[d];
}

// ---------------- W1 split: [500,128] fp32 -> [512][128] bf16 hi/lo ----------------
__global__ void k_wsplit(const float* __restrict__ W1) {
    int idx = blockIdx.x * 256 + threadIdx.x;     // 65536 = 512*128
    int k = idx >> 7, n = idx & 127;
    float v = (k < IN_DIM) ? W1[(size_t)k * HID_DIM + n] : 0.f;
    __nv_bfloat16 h = __float2bfloat16(v);
    float r = v - __bfloat162float(h);
    g_w1hi[idx] = h;
    g_w1lo[idx] = __float2bfloat16(r);
}

// ---------------- GEMM1 via wmma bf16 3-term: g_h1 = x @ W1 ----------------
// CTA 128x128, 8 warps of 32x64, K chunks of 16.
__global__ __launch_bounds__(256) void k_gemm1_mma(const float* __restrict__ X) {
    __shared__ __nv_bfloat16 Ah[128][24];
    __shared__ __nv_bfloat16 Al[128][24];
    __shared__ __nv_bfloat16 Bh[16][136];
    __shared__ __nv_bfloat16 Bl[16][136];

    int t = threadIdx.x;
    int wid = t >> 5;
    int warp_m = wid & 3;       // 0..3 : rows warp_m*32
    int warp_n = wid >> 2;      // 0..1 : cols warp_n*64
    int row0 = blockIdx.x * 128;

    wmma::fragment<wmma::accumulator, 16, 16, 16, float> acc[2][4];
    #pragma unroll
    for (int i = 0; i < 2; i++)
        #pragma unroll
        for (int j = 0; j < 4; j++) wmma::fill_fragment(acc[i][j], 0.f);

    int arow = t >> 1, aseg = t & 1;                 // A: row, 8-wide k segment
    const float* xrow = X + (size_t)(row0 + arow) * IN_DIM;
    bool rvalid = (row0 + arow) < N_NODES;
    int bk = t >> 4, bn0 = (t & 15) << 3;            // B: k row, 8-wide n segment

    for (int c = 0; c < 32; c++) {
        // A tile: fp32 -> bf16 hi/lo split
        #pragma unroll
        for (int h = 0; h < 2; h++) {
            int kl = aseg * 8 + h * 4;
            int gk = c * 16 + kl;
            float4 v = make_float4(0.f, 0.f, 0.f, 0.f);
            if (rvalid && gk < IN_DIM) v = *(const float4*)(xrow + gk);
            __nv_bfloat16 h0 = __float2bfloat16(v.x), h1 = __float2bfloat16(v.y);
            __nv_bfloat16 h2 = __float2bfloat16(v.z), h3 = __float2bfloat16(v.w);
            __nv_bfloat16 l0 = __float2bfloat16(v.x - __bfloat162float(h0));
            __nv_bfloat16 l1 = __float2bfloat16(v.y - __bfloat162float(h1));
            __nv_bfloat16 l2 = __float2bfloat16(v.z - __bfloat162float(h2));
            __nv_bfloat16 l3 = __float2bfloat16(v.w - __bfloat162float(h3));
            uint2 hw = make_uint2(
                (uint32_t)__bfloat16_as_ushort(h0) | ((uint32_t)__bfloat16_as_ushort(h1) << 16),
                (uint32_t)__bfloat16_as_ushort(h2) | ((uint32_t)__bfloat16_as_ushort(h3) << 16));
            uint2 lw = make_uint2(
                (uint32_t)__bfloat16_as_ushort(l0) | ((uint32_t)__bfloat16_as_ushort(l1) << 16),
                (uint32_t)__bfloat16_as_ushort(l2) | ((uint32_t)__bfloat16_as_ushort(l3) << 16));
            *(uint2*)&Ah[arow][kl] = hw;
            *(uint2*)&Al[arow][kl] = lw;
        }
        // B tile: copy pre-split bf16
        {
            size_t off = (size_t)(c * 16 + bk) * HID_DIM + bn0;
            *(uint4*)&Bh[bk][bn0] = *(const uint4*)(g_w1hi + off);
            *(uint4*)&Bl[bk][bn0] = *(const uint4*)(g_w1lo + off);
        }
        __syncthreads();

        wmma::fragment<wmma::matrix_a, 16, 16, 16, __nv_bfloat16, wmma::row_major> ah[2], al[2];
        #pragma unroll
        for (int i = 0; i < 2; i++) {
            wmma::load_matrix_sync(ah[i], &Ah[warp_m * 32 + i * 16][0], 24);
            wmma::load_matrix_sync(al[i], &Al[warp_m * 32 + i * 16][0], 24);
        }
        #pragma unroll
        for (int j = 0; j < 4; j++) {
            wmma::fragment<wmma::matrix_b, 16, 16, 16, __nv_bfloat16, wmma::row_major> bh, bl;
            int col = warp_n * 64 + j * 16;
            wmma::load_matrix_sync(bh, &Bh[0][col], 136);
            wmma::load_matrix_sync(bl, &Bl[0][col], 136);
            #pragma unroll
            for (int i = 0; i < 2; i++) {
                wmma::mma_sync(acc[i][j], ah[i], bh, acc[i][j]);
                wmma::mma_sync(acc[i][j], ah[i], bl, acc[i][j]);
                wmma::mma_sync(acc[i][j], al[i], bh, acc[i][j]);
            }
        }
        __syncthreads();
    }

    // epilogue: g_h1 is padded to N_PAD rows, no bounds checks needed
    #pragma unroll
    for (int i = 0; i < 2; i++)
        #pragma unroll
        for (int j = 0; j < 4; j++) {
            size_t off = (size_t)(row0 + warp_m * 32 + i * 16) * HID_DIM + warp_n * 64 + j * 16;
            wmma::store_matrix_sync(&g_h1[off], acc[i][j], HID_DIM, wmma::mem_row_major);
        }
}

// ---------------- aggregation 1 ----------------
__global__ __launch_bounds__(256) void k_agg1(const float* __restrict__ b1) {
    int node = blockIdx.x * 8 + (threadIdx.x >> 5);
    if (node >= N_NODES) return;
    int lane = threadIdx.x & 31;
    const float4* h = (const float4*)g_h1;

    float di = g_dinv[node];
    float ws = di * di;
    float4 acc = h[(size_t)node * 32 + lane];
    acc.x *= ws; acc.y *= ws; acc.z *= ws; acc.w *= ws;

    int p0 = g_rowptr[node], p1 = g_rowptr[node + 1];
    for (int p = p0; p < p1; p++) {
        int s  = g_csr_src[p];
        float w = g_csr_w[p];
        float4 v = h[(size_t)s * 32 + lane];
        acc.x += w * v.x; acc.y += w * v.y; acc.z += w * v.z; acc.w += w * v.w;
    }
    float4 bb = ((const float4*)b1)[lane];
    float4 o;
    o.x = fmaxf(acc.x + bb.x, 0.f);
    o.y = fmaxf(acc.y + bb.y, 0.f);
    o.z = fmaxf(acc.z + bb.z, 0.f);
    o.w = fmaxf(acc.w + bb.w, 0.f);
    ((float4*)g_a1)[(size_t)node * 32 + lane] = o;
}

// ---------------- GEMM2 ----------------
__global__ __launch_bounds__(256) void k_gemm2(const float* __restrict__ W2) {
    __shared__ float Hs[32][129];
    __shared__ float Ws[128][40];
    int t = threadIdx.x;
    int row0 = blockIdx.x * 32;

    #pragma unroll
    for (int j = 0; j < 20; j++) {
        int i = t + j * 256;
        Ws[i / 40][i % 40] = W2[i];
    }
    #pragma unroll
    for (int j = 0; j < 16; j++) {
        int i = t + j * 256;
        int r = i >> 7, c = i & 127;
        int gr = row0 + r;
        Hs[r][c] = (gr < N_NODES) ? g_a1[(size_t)gr * HID_DIM + c] : 0.f;
    }
    __syncthreads();

    int r = t >> 3;
    int c0 = (t & 7) * 5;
    float acc[5] = {0.f, 0.f, 0.f, 0.f, 0.f};
    #pragma unroll 8
    for (int k = 0; k < 128; k++) {
        float a = Hs[r][k];
        #pragma unroll
        for (int j = 0; j < 5; j++) acc[j] += a * Ws[k][c0 + j];
    }
    int gr = row0 + r;
    if (gr < N_NODES) {
        #pragma unroll
        for (int j = 0; j < 5; j++)
            g_h2[(size_t)gr * OUT_DIM + c0 + j] = acc[j];
    }
}

// ---------------- aggregation 2 + log_softmax ----------------
__global__ __launch_bounds__(256) void k_agg2(const float* __restrict__ b2,
                                              float* __restrict__ out) {
    int node = blockIdx.x * 8 + (threadIdx.x >> 5);
    if (node >= N_NODES) return;
    int lane = threadIdx.x & 31;

    float di = g_dinv[node];
    float ws = di * di;
    float acc0, acc1 = 0.f;
    {
        size_t b = (size_t)node * OUT_DIM;
        acc0 = ws * g_h2[b + lane];
        if (lane < 8) acc1 = ws * g_h2[b + 32 + lane];
    }
    int p0 = g_rowptr[node], p1 = g_rowptr[node + 1];
    for (int p = p0; p < p1; p++) {
        int s  = g_csr_src[p];
        float w = g_csr_w[p];
        size_t b = (size_t)s * OUT_DIM;
        acc0 += w * g_h2[b + lane];
        if (lane < 8) acc1 += w * g_h2[b + 32 + lane];
    }
    acc0 += b2[lane];
    if (lane < 8) acc1 += b2[32 + lane];

    float m = acc0;
    if (lane < 8) m = fmaxf(m, acc1);
    #pragma unroll
    for (int o = 16; o; o >>= 1) m = fmaxf(m, __shfl_xor_sync(0xffffffffu, m, o));
    float s = __expf(acc0 - m) + ((lane < 8) ? __expf(acc1 - m) : 0.f);
    #pragma unroll
    for (int o = 16; o; o >>= 1) s += __shfl_xor_sync(0xffffffffu, s, o);
    float ls = __logf(s);

    out[(size_t)node * OUT_DIM + lane] = acc0 - m - ls;
    if (lane < 8) out[(size_t)node * OUT_DIM + 32 + lane] = acc1 - m - ls;
}

// ---------------- launch ----------------
extern "C" void kernel_launch(void* const* d_in, const int* in_sizes, int n_in,
                              void* d_out, int out_size) {
    const float* x  = (const float*)d_in[0];
    const void*  ei = d_in[1];
    const float* W1 = (const float*)d_in[2];
    const float* b1 = (const float*)d_in[3];
    const float* W2 = (const float*)d_in[4];
    const float* b2 = (const float*)d_in[5];
    float*       out = (float*)d_out;

    const int TB = 256;
    int nb_nodes = (N_NODES + TB - 1) / TB;
    int nb_edges = (N_EDGES + TB - 1) / TB;
    int nb_scan  = (N_NODES + 1023) / 1024;   // 98

    k_detect<<<1, 1>>>(ei);
    k_init<<<nb_nodes, TB>>>();
    k_degree<<<nb_edges, TB>>>(ei);
    k_dinv<<<nb_nodes, TB>>>();
    k_scan1<<<nb_scan, 1024>>>();
    k_scan2<<<1, 128>>>(nb_scan);
    k_scan3<<<nb_nodes, TB>>>();
    k_scatter<<<nb_edges, TB>>>(ei);

    k_wsplit<<<(K_PAD * HID_DIM) / TB, TB>>>(W1);
    k_gemm1_mma<<<N_PAD / 128, 256>>>(x);
    k_agg1<<<(N_NODES + 7) / 8, 256>>>(b1);
    k_gemm2<<<(N_NODES + 31) / 32, 256>>>(W2);
    k_agg2<<<(N_NODES + 7) / 8, 256>>>(b2, out);
}

// round 11
// speedup vs baseline: 2.0660x; 1.7312x over previous
#include <cuda_runtime.h>
#include <cuda_bf16.h>
#include <cuda_pipeline_primitives.h>
#include <mma.h>
#include <math.h>
#include <stdint.h>

using namespace nvcuda;

#define N_NODES 100000
#define N_PAD   100096          // 782 * 128
#define N_EDGES 1600000
#define IN_DIM  500
#define HID_DIM 128
#define OUT_DIM 40
#define OUT_PAD 64
#define K_PAD   512

// ---------------- scratch ----------------
__device__ int   g_is64;
__device__ __align__(256) int   g_deg[N_NODES];
__device__ __align__(256) int   g_cursor[N_NODES];
__device__ __align__(256) float g_dinv[N_NODES];
__device__ __align__(256) int   g_rowptr[N_NODES + 1];
__device__ __align__(256) int   g_bsum[128];
__device__ __align__(256) int   g_csr_src[N_EDGES];
__device__ __align__(256) __nv_bfloat16 g_w1hi[K_PAD * HID_DIM];   // [k][n]
__device__ __align__(256) __nv_bfloat16 g_w1lo[K_PAD * HID_DIM];
__device__ __align__(256) __nv_bfloat16 g_w2hi[HID_DIM * OUT_PAD]; // [k][n] padded
__device__ __align__(256) __nv_bfloat16 g_w2lo[HID_DIM * OUT_PAD];
__device__ __align__(256) float g_h1[(size_t)N_PAD * HID_DIM];
__device__ __align__(256) __nv_bfloat16 g_a1hi[(size_t)N_PAD * HID_DIM];
__device__ __align__(256) __nv_bfloat16 g_a1lo[(size_t)N_PAD * HID_DIM];
__device__ __align__(256) float g_h2p[(size_t)N_PAD * OUT_PAD];

// ---------------- edge decode ----------------
__device__ __forceinline__ int edge_id(const void* ei, size_t idx) {
    if (g_is64) return (int)((const long long*)ei)[idx];
    return ((const int*)ei)[idx];
}
__global__ void k_detect(const void* ei) {
    const long long* p = (const long long*)ei;
    int is64 = 1;
    for (int i = 0; i < 16; i++) {
        long long v = p[i];
        if (v < 0 || v >= N_NODES) { is64 = 0; break; }
    }
    g_is64 = is64;
}

// ---------------- weight splits ----------------
__global__ void k_wsplit(const float* __restrict__ W1) {
    int idx = blockIdx.x * 256 + threadIdx.x;     // 65536 = 512*128
    int k = idx >> 7, n = idx & 127;
    float v = (k < IN_DIM) ? W1[(size_t)k * HID_DIM + n] : 0.f;
    __nv_bfloat16 h = __float2bfloat16(v);
    g_w1hi[idx] = h;
    g_w1lo[idx] = __float2bfloat16(v - __bfloat162float(h));
}
__global__ void k_w2split(const float* __restrict__ W2) {
    int idx = blockIdx.x * 256 + threadIdx.x;     // 8192 = 128*64
    int k = idx >> 6, n = idx & 63;
    float v = (n < OUT_DIM) ? W2[(size_t)k * OUT_DIM + n] : 0.f;
    __nv_bfloat16 h = __float2bfloat16(v);
    g_w2hi[idx] = h;
    g_w2lo[idx] = __float2bfloat16(v - __bfloat162float(h));
}

// ---------------- GEMM1: g_h1 = x @ W1, wmma bf16 3-term, KC=32, cp.async B ----------------
__global__ __launch_bounds__(256) void k_gemm1_mma(const float* __restrict__ X) {
    __shared__ __nv_bfloat16 Ah[128][40];
    __shared__ __nv_bfloat16 Al[128][40];
    __shared__ __nv_bfloat16 Bh[32][136];
    __shared__ __nv_bfloat16 Bl[32][136];

    int t = threadIdx.x;
    int wid = t >> 5;
    int warp_m = wid & 3;       // rows warp_m*32
    int warp_n = wid >> 2;      // cols warp_n*64
    int row0 = blockIdx.x * 128;

    wmma::fragment<wmma::accumulator, 16, 16, 16, float> acc[2][4];
    #pragma unroll
    for (int i = 0; i < 2; i++)
        #pragma unroll
        for (int j = 0; j < 4; j++) wmma::fill_fragment(acc[i][j], 0.f);

    int arow = t >> 1, aseg = t & 1;                 // A: row, 16-wide k segment
    const float* xrow = X + (size_t)(row0 + arow) * IN_DIM;
    bool rvalid = (row0 + arow) < N_NODES;
    int bk = t >> 3, bn0 = (t & 7) << 4;             // B: k row (0..31), 16-wide n seg

    for (int c = 0; c < 16; c++) {
        // B tiles via cp.async (overlaps with A conversion below)
        {
            size_t off = (size_t)(c * 32 + bk) * HID_DIM + bn0;
            __pipeline_memcpy_async(&Bh[bk][bn0],     g_w1hi + off,     16);
            __pipeline_memcpy_async(&Bh[bk][bn0 + 8], g_w1hi + off + 8, 16);
            __pipeline_memcpy_async(&Bl[bk][bn0],     g_w1lo + off,     16);
            __pipeline_memcpy_async(&Bl[bk][bn0 + 8], g_w1lo + off + 8, 16);
            __pipeline_commit();
        }
        // A tile: fp32 -> bf16 hi/lo split (16 floats per thread)
        int kbase = c * 32 + aseg * 16;
        #pragma unroll
        for (int h = 0; h < 4; h++) {
            int gk = kbase + h * 4;
            float4 v = make_float4(0.f, 0.f, 0.f, 0.f);
            if (rvalid && gk < IN_DIM) v = *(const float4*)(xrow + gk);
            __nv_bfloat16 h0 = __float2bfloat16(v.x), h1 = __float2bfloat16(v.y);
            __nv_bfloat16 h2 = __float2bfloat16(v.z), h3 = __float2bfloat16(v.w);
            __nv_bfloat16 l0 = __float2bfloat16(v.x - __bfloat162float(h0));
            __nv_bfloat16 l1 = __float2bfloat16(v.y - __bfloat162float(h1));
            __nv_bfloat16 l2 = __float2bfloat16(v.z - __bfloat162float(h2));
            __nv_bfloat16 l3 = __float2bfloat16(v.w - __bfloat162float(h3));
            uint2 hw = make_uint2(
                (uint32_t)__bfloat16_as_ushort(h0) | ((uint32_t)__bfloat16_as_ushort(h1) << 16),
                (uint32_t)__bfloat16_as_ushort(h2) | ((uint32_t)__bfloat16_as_ushort(h3) << 16));
            uint2 lw = make_uint2(
                (uint32_t)__bfloat16_as_ushort(l0) | ((uint32_t)__bfloat16_as_ushort(l1) << 16),
                (uint32_t)__bfloat16_as_ushort(l2) | ((uint32_t)__bfloat16_as_ushort(l3) << 16));
            *(uint2*)&Ah[arow][aseg * 16 + h * 4] = hw;
            *(uint2*)&Al[arow][aseg * 16 + h * 4] = lw;
        }
        __pipeline_wait_prior(0);
        __syncthreads();

        #pragma unroll
        for (int ks = 0; ks < 2; ks++) {
            wmma::fragment<wmma::matrix_a, 16, 16, 16, __nv_bfloat16, wmma::row_major> ah[2], al[2];
            #pragma unroll
            for (int i = 0; i < 2; i++) {
                wmma::load_matrix_sync(ah[i], &Ah[warp_m * 32 + i * 16][ks * 16], 40);
                wmma::load_matrix_sync(al[i], &Al[warp_m * 32 + i * 16][ks * 16], 40);
            }
            #pragma unroll
            for (int j = 0; j < 4; j++) {
                wmma::fragment<wmma::matrix_b, 16, 16, 16, __nv_bfloat16, wmma::row_major> bh, bl;
                int col = warp_n * 64 + j * 16;
                wmma::load_matrix_sync(bh, &Bh[ks * 16][col], 136);
                wmma::load_matrix_sync(bl, &Bl[ks * 16][col], 136);
                #pragma unroll
                for (int i = 0; i < 2; i++) {
                    wmma::mma_sync(acc[i][j], ah[i], bh, acc[i][j]);
                    wmma::mma_sync(acc[i][j], ah[i], bl, acc[i][j]);
                    wmma::mma_sync(acc[i][j], al[i], bh, acc[i][j]);
                }
            }
        }
        __syncthreads();
    }

    #pragma unroll
    for (int i = 0; i < 2; i++)
        #pragma unroll
        for (int j = 0; j < 4; j++) {
            size_t off = (size_t)(row0 + warp_m * 32 + i * 16) * HID_DIM + warp_n * 64 + j * 16;
            wmma::store_matrix_sync(&g_h1[off], acc[i][j], HID_DIM, wmma::mem_row_major);
        }
}

// ---------------- preprocessing ----------------
__global__ void k_init() {
    int i = blockIdx.x * 256 + threadIdx.x;
    if (i < N_NODES) { g_deg[i] = 0; g_cursor[i] = 0; }
}
__global__ void k_degree(const void* __restrict__ ei) {
    int e = blockIdx.x * 256 + threadIdx.x;
    if (e >= N_EDGES) return;
    int d = edge_id(ei, (size_t)N_EDGES + e);
    if ((unsigned)d < N_NODES) atomicAdd(&g_deg[d], 1);
}
__global__ void k_dinv() {
    int i = blockIdx.x * 256 + threadIdx.x;
    if (i < N_NODES) g_dinv[i] = rsqrtf((float)(g_deg[i] + 1));
}
__global__ __launch_bounds__(1024) void k_scan1() {
    __shared__ int wsum[32];
    int t = threadIdx.x, lane = t & 31, w = t >> 5;
    int idx = blockIdx.x * 1024 + t;
    int v = (idx < N_NODES) ? g_deg[idx] : 0;
    int x = v;
    #pragma unroll
    for (int d = 1; d < 32; d <<= 1) {
        int y = __shfl_up_sync(0xffffffffu, x, d);
        if (lane >= d) x += y;
    }
    if (lane == 31) wsum[w] = x;
    __syncthreads();
    if (w == 0) {
        int s = wsum[lane];
        #pragma unroll
        for (int d = 1; d < 32; d <<= 1) {
            int y = __shfl_up_sync(0xffffffffu, s, d);
            if (lane >= d) s += y;
        }
        wsum[lane] = s;
    }
    __syncthreads();
    int woff = w ? wsum[w - 1] : 0;
    if (idx < N_NODES) g_rowptr[idx] = woff + x - v;
    if (t == 1023) g_bsum[blockIdx.x] = wsum[31];
}
__global__ void k_scan2(int nb) {
    __shared__ int ws[4];
    __shared__ int tot;
    int t = threadIdx.x, lane = t & 31, w = t >> 5;
    int v = (t < nb) ? g_bsum[t] : 0;
    int x = v;
    #pragma unroll
    for (int d = 1; d < 32; d <<= 1) {
        int y = __shfl_up_sync(0xffffffffu, x, d);
        if (lane >= d) x += y;
    }
    if (lane == 31) ws[w] = x;
    __syncthreads();
    if (t == 0) {
        int s = 0;
        #pragma unroll
        for (int i = 0; i < 4; i++) { int tv = ws[i]; ws[i] = s; s += tv; }
        tot = s;
    }
    __syncthreads();
    if (t < nb) g_bsum[t] = ws[w] + x - v;
    if (t == 0) g_rowptr[N_NODES] = tot;
}
__global__ void k_scan3() {
    int idx = blockIdx.x * 256 + threadIdx.x;
    if (idx < N_NODES) g_rowptr[idx] += g_bsum[idx >> 10];
}
__global__ void k_scatter(const void* __restrict__ ei) {
    int e = blockIdx.x * 256 + threadIdx.x;
    if (e >= N_EDGES) return;
    int s = edge_id(ei, e);
    int d = edge_id(ei, (size_t)N_EDGES + e);
    if ((unsigned)s >= N_NODES || (unsigned)d >= N_NODES) return;
    int p = g_rowptr[d] + atomicAdd(&g_cursor[d], 1);
    g_csr_src[p] = s;
}

// ---------------- aggregation 1: relu(agg + b1), writes bf16 hi/lo ----------------
__global__ __launch_bounds__(256) void k_agg1(const float* __restrict__ b1) {
    int node = blockIdx.x * 8 + (threadIdx.x >> 5);
    if (node >= N_NODES) return;
    int lane = threadIdx.x & 31;
    const float4* h = (const float4*)g_h1;

    float dn = g_dinv[node];
    float4 acc = h[(size_t)node * 32 + lane];
    acc.x *= dn; acc.y *= dn; acc.z *= dn; acc.w *= dn;   // dinv_d * h_node

    int p0 = g_rowptr[node], p1 = g_rowptr[node + 1];
    for (int p = p0; p < p1; p++) {
        int s  = g_csr_src[p];
        float w = g_dinv[s];
        float4 v = h[(size_t)s * 32 + lane];
        acc.x += w * v.x; acc.y += w * v.y; acc.z += w * v.z; acc.w += w * v.w;
    }
    float4 bb = ((const float4*)b1)[lane];
    float4 o;
    o.x = fmaxf(fmaf(dn, acc.x, bb.x), 0.f);
    o.y = fmaxf(fmaf(dn, acc.y, bb.y), 0.f);
    o.z = fmaxf(fmaf(dn, acc.z, bb.z), 0.f);
    o.w = fmaxf(fmaf(dn, acc.w, bb.w), 0.f);

    __nv_bfloat16 h0 = __float2bfloat16(o.x), h1v = __float2bfloat16(o.y);
    __nv_bfloat16 h2 = __float2bfloat16(o.z), h3 = __float2bfloat16(o.w);
    __nv_bfloat16 l0 = __float2bfloat16(o.x - __bfloat162float(h0));
    __nv_bfloat16 l1 = __float2bfloat16(o.y - __bfloat162float(h1v));
    __nv_bfloat16 l2 = __float2bfloat16(o.z - __bfloat162float(h2));
    __nv_bfloat16 l3 = __float2bfloat16(o.w - __bfloat162float(h3));
    uint2 hw = make_uint2(
        (uint32_t)__bfloat16_as_ushort(h0) | ((uint32_t)__bfloat16_as_ushort(h1v) << 16),
        (uint32_t)__bfloat16_as_ushort(h2) | ((uint32_t)__bfloat16_as_ushort(h3) << 16));
    uint2 lw = make_uint2(
        (uint32_t)__bfloat16_as_ushort(l0) | ((uint32_t)__bfloat16_as_ushort(l1) << 16),
        (uint32_t)__bfloat16_as_ushort(l2) | ((uint32_t)__bfloat16_as_ushort(l3) << 16));
    *(uint2*)&g_a1hi[(size_t)node * HID_DIM + lane * 4] = hw;
    *(uint2*)&g_a1lo[(size_t)node * HID_DIM + lane * 4] = lw;
}

// ---------------- GEMM2: g_h2p = a1 @ W2, wmma bf16 3-term ----------------
__global__ __launch_bounds__(256) void k_gemm2_mma() {
    __shared__ __nv_bfloat16 Ah[128][40];
    __shared__ __nv_bfloat16 Al[128][40];
    __shared__ __nv_bfloat16 Bh[32][72];
    __shared__ __nv_bfloat16 Bl[32][72];

    int t = threadIdx.x;
    int wid = t >> 5;           // rows wid*16
    int row0 = blockIdx.x * 128;

    wmma::fragment<wmma::accumulator, 16, 16, 16, float> acc[4];
    #pragma unroll
    for (int j = 0; j < 4; j++) wmma::fill_fragment(acc[j], 0.f);

    int arow = t >> 1, aseg = t & 1;
    int bk = t >> 3, bn0 = (t & 7) << 3;

    for (int c = 0; c < 4; c++) {
        {
            size_t aoff = (size_t)(row0 + arow) * HID_DIM + c * 32 + aseg * 16;
            __pipeline_memcpy_async(&Ah[arow][aseg * 16],     g_a1hi + aoff,     16);
            __pipeline_memcpy_async(&Ah[arow][aseg * 16 + 8], g_a1hi + aoff + 8, 16);
            __pipeline_memcpy_async(&Al[arow][aseg * 16],     g_a1lo + aoff,     16);
            __pipeline_memcpy_async(&Al[arow][aseg * 16 + 8], g_a1lo + aoff + 8, 16);
            size_t boff = (size_t)(c * 32 + bk) * OUT_PAD + bn0;
            __pipeline_memcpy_async(&Bh[bk][bn0], g_w2hi + boff, 16);
            __pipeline_memcpy_async(&Bl[bk][bn0], g_w2lo + boff, 16);
            __pipeline_commit();
        }
        __pipeline_wait_prior(0);
        __syncthreads();

        #pragma unroll
        for (int ks = 0; ks < 2; ks++) {
            wmma::fragment<wmma::matrix_a, 16, 16, 16, __nv_bfloat16, wmma::row_major> ah, al;
            wmma::load_matrix_sync(ah, &Ah[wid * 16][ks * 16], 40);
            wmma::load_matrix_sync(al, &Al[wid * 16][ks * 16], 40);
            #pragma unroll
            for (int j = 0; j < 4; j++) {
                wmma::fragment<wmma::matrix_b, 16, 16, 16, __nv_bfloat16, wmma::row_major> bh, bl;
                wmma::load_matrix_sync(bh, &Bh[ks * 16][j * 16], 72);
                wmma::load_matrix_sync(bl, &Bl[ks * 16][j * 16], 72);
                wmma::mma_sync(acc[j], ah, bh, acc[j]);
                wmma::mma_sync(acc[j], ah, bl, acc[j]);
                wmma::mma_sync(acc[j], al, bh, acc[j]);
            }
        }
        __syncthreads();
    }

    #pragma unroll
    for (int j = 0; j < 4; j++) {
        size_t off = (size_t)(row0 + wid * 16) * OUT_PAD + j * 16;
        wmma::store_matrix_sync(&g_h2p[off], acc[j], OUT_PAD, wmma::mem_row_major);
    }
}

// ---------------- aggregation 2 + bias + log_softmax ----------------
__global__ __launch_bounds__(256) void k_agg2(const float* __restrict__ b2,
                                              float* __restrict__ out) {
    int node = blockIdx.x * 8 + (threadIdx.x >> 5);
    if (node >= N_NODES) return;
    int lane = threadIdx.x & 31;

    float dn = g_dinv[node];
    float acc0, acc1 = 0.f;
    {
        size_t b = (size_t)node * OUT_PAD;
        acc0 = dn * g_h2p[b + lane];
        if (lane < 8) acc1 = dn * g_h2p[b + 32 + lane];
    }
    int p0 = g_rowptr[node], p1 = g_rowptr[node + 1];
    for (int p = p0; p < p1; p++) {
        int s  = g_csr_src[p];
        float w = g_dinv[s];
        size_t b = (size_t)s * OUT_PAD;
        acc0 += w * g_h2p[b + lane];
        if (lane < 8) acc1 += w * g_h2p[b + 32 + lane];
    }
    acc0 = fmaf(dn, acc0, b2[lane]);
    if (lane < 8) acc1 = fmaf(dn, acc1, b2[32 + lane]);

    float m = acc0;
    if (lane < 8) m = fmaxf(m, acc1);
    #pragma unroll
    for (int o = 16; o; o >>= 1) m = fmaxf(m, __shfl_xor_sync(0xffffffffu, m, o));
    float s = __expf(acc0 - m) + ((lane < 8) ? __expf(acc1 - m) : 0.f);
    #pragma unroll
    for (int o = 16; o; o >>= 1) s += __shfl_xor_sync(0xffffffffu, s, o);
    float ls = __logf(s);

    out[(size_t)node * OUT_DIM + lane] = acc0 - m - ls;
    if (lane < 8) out[(size_t)node * OUT_DIM + 32 + lane] = acc1 - m - ls;
}

// ---------------- launch ----------------
extern "C" void kernel_launch(void* const* d_in, const int* in_sizes, int n_in,
                              void* d_out, int out_size) {
    const float* x  = (const float*)d_in[0];
    const void*  ei = d_in[1];
    const float* W1 = (const float*)d_in[2];
    const float* b1 = (const float*)d_in[3];
    const float* W2 = (const float*)d_in[4];
    const float* b2 = (const float*)d_in[5];
    float*       out = (float*)d_out;

    const int TB = 256;
    int nb_nodes = (N_NODES + TB - 1) / TB;
    int nb_edges = (N_EDGES + TB - 1) / TB;
    int nb_scan  = (N_NODES + 1023) / 1024;   // 98

    // Order chosen so k_gemm1_mma is my launch index 3 (= ncu's captured slot).
    k_detect<<<1, 1>>>(ei);                       // 0
    k_wsplit<<<(K_PAD * HID_DIM) / TB, TB>>>(W1); // 1
    k_w2split<<<(HID_DIM * OUT_PAD) / TB, TB>>>(W2); // 2
    k_gemm1_mma<<<N_PAD / 128, 256>>>(x);         // 3  <- profiled
    k_init<<<nb_nodes, TB>>>();                   // 4
    k_degree<<<nb_edges, TB>>>(ei);               // 5
    k_dinv<<<nb_nodes, TB>>>();                   // 6
    k_scan1<<<nb_scan, 1024>>>();
    k_scan2<<<1, 128>>>(nb_scan);
    k_scan3<<<nb_nodes, TB>>>();
    k_scatter<<<nb_edges, TB>>>(ei);
    k_agg1<<<(N_NODES + 7) / 8, 256>>>(b1);
    k_gemm2_mma<<<N_PAD / 128, 256>>>();
    k_agg2<<<(N_NODES + 7) / 8, 256>>>(b2, out);
}

// round 12
// speedup vs baseline: 2.2194x; 1.0743x over previous
#include <cuda_runtime.h>
#include <cuda_bf16.h>
#include <cuda_pipeline_primitives.h>
#include <mma.h>
#include <math.h>
#include <stdint.h>

using namespace nvcuda;

#define N_NODES 100000
#define N_PAD   100096          // 782 * 128
#define N_EDGES 1600000
#define IN_DIM  500
#define HID_DIM 128
#define OUT_DIM 40
#define OUT_PAD 64
#define K_PAD   512

// ---------------- scratch ----------------
__device__ int   g_is64;
__device__ __align__(256) int   g_deg[N_NODES];
__device__ __align__(256) int   g_cursor[N_NODES];
__device__ __align__(256) float g_dinv[N_NODES];
__device__ __align__(256) int   g_rowptr[N_NODES + 1];
__device__ __align__(256) int   g_bsum[128];
__device__ __align__(256) int   g_csr_src[N_EDGES];
__device__ __align__(256) __nv_bfloat16 g_w1hi[K_PAD * HID_DIM];   // [k][n]
__device__ __align__(256) __nv_bfloat16 g_w1lo[K_PAD * HID_DIM];
__device__ __align__(256) __nv_bfloat16 g_w2hi[HID_DIM * OUT_PAD]; // [k][n] padded
__device__ __align__(256) __nv_bfloat16 g_w2lo[HID_DIM * OUT_PAD];
__device__ __align__(256) float g_h1[(size_t)N_PAD * HID_DIM];
__device__ __align__(256) __nv_bfloat16 g_a1hi[(size_t)N_PAD * HID_DIM];
__device__ __align__(256) __nv_bfloat16 g_a1lo[(size_t)N_PAD * HID_DIM];
__device__ __align__(256) float g_h2p[(size_t)N_PAD * OUT_PAD];

// ---------------- edge decode ----------------
__device__ __forceinline__ int edge_id(const void* ei, size_t idx) {
    if (g_is64) return (int)((const long long*)ei)[idx];
    return ((const int*)ei)[idx];
}
__global__ void k_detect(const void* ei) {
    const long long* p = (const long long*)ei;
    int is64 = 1;
    for (int i = 0; i < 16; i++) {
        long long v = p[i];
        if (v < 0 || v >= N_NODES) { is64 = 0; break; }
    }
    g_is64 = is64;
}

// ---------------- weight splits ----------------
__global__ void k_wsplit(const float* __restrict__ W1) {
    int idx = blockIdx.x * 256 + threadIdx.x;     // 65536 = 512*128
    int k = idx >> 7, n = idx & 127;
    float v = (k < IN_DIM) ? W1[(size_t)k * HID_DIM + n] : 0.f;
    __nv_bfloat16 h = __float2bfloat16(v);
    g_w1hi[idx] = h;
    g_w1lo[idx] = __float2bfloat16(v - __bfloat162float(h));
}
__global__ void k_w2split(const float* __restrict__ W2) {
    int idx = blockIdx.x * 256 + threadIdx.x;     // 8192 = 128*64
    int k = idx >> 6, n = idx & 63;
    float v = (n < OUT_DIM) ? W2[(size_t)k * OUT_DIM + n] : 0.f;
    __nv_bfloat16 h = __float2bfloat16(v);
    g_w2hi[idx] = h;
    g_w2lo[idx] = __float2bfloat16(v - __bfloat162float(h));
}

// ---------------- GEMM1: g_h1 = x @ W1, wmma bf16 3-term, 2-stage pipeline ----------------
// Dynamic smem layout (bf16 elems):
//   Ah[2][128][40] @ 0       Al[2][128][40] @ 10240
//   Bh[2][32][136] @ 20480   Bl[2][32][136] @ 29184
#define G1_SMEM_BYTES ((20480 + 2 * 8704) * 2)   // 75776 B

__global__ __launch_bounds__(256) void k_gemm1_mma(const float* __restrict__ X) {
    extern __shared__ __nv_bfloat16 sm[];
    __nv_bfloat16* Ah = sm;
    __nv_bfloat16* Al = sm + 10240;
    __nv_bfloat16* Bh = sm + 20480;
    __nv_bfloat16* Bl = sm + 20480 + 8704;

    int t = threadIdx.x;
    int wid = t >> 5;
    int warp_m = wid & 3;       // rows warp_m*32
    int warp_n = wid >> 2;      // cols warp_n*64
    int row0 = blockIdx.x * 128;

    wmma::fragment<wmma::accumulator, 16, 16, 16, float> acc[2][4];
    #pragma unroll
    for (int i = 0; i < 2; i++)
        #pragma unroll
        for (int j = 0; j < 4; j++) wmma::fill_fragment(acc[i][j], 0.f);

    int arow = t >> 1, aseg = t & 1;                 // A: row, 16-wide k segment
    const float* xrow = X + (size_t)(row0 + arow) * IN_DIM;
    bool rvalid = (row0 + arow) < N_NODES;
    int bk = t >> 3, bn0 = (t & 7) << 4;             // B: k row (0..31), 16-wide n seg

    float4 areg[4];

    // prefetch chunk 0
    {
        int kbase = aseg * 16;
        #pragma unroll
        for (int h = 0; h < 4; h++) {
            int gk = kbase + h * 4;
            areg[h] = make_float4(0.f, 0.f, 0.f, 0.f);
            if (rvalid && gk < IN_DIM) areg[h] = *(const float4*)(xrow + gk);
        }
        size_t off = (size_t)bk * HID_DIM + bn0;
        __nv_bfloat16* bh = Bh + bk * 136 + bn0;
        __nv_bfloat16* bl = Bl + bk * 136 + bn0;
        __pipeline_memcpy_async(bh,     g_w1hi + off,     16);
        __pipeline_memcpy_async(bh + 8, g_w1hi + off + 8, 16);
        __pipeline_memcpy_async(bl,     g_w1lo + off,     16);
        __pipeline_memcpy_async(bl + 8, g_w1lo + off + 8, 16);
        __pipeline_commit();
    }

    for (int c = 0; c < 16; c++) {
        int s = c & 1;
        // convert prefetched A regs -> stage s
        {
            __nv_bfloat16* ah = Ah + s * 5120 + arow * 40 + aseg * 16;
            __nv_bfloat16* al = Al + s * 5120 + arow * 40 + aseg * 16;
            #pragma unroll
            for (int h = 0; h < 4; h++) {
                float4 v = areg[h];
                __nv_bfloat16 h0 = __float2bfloat16(v.x), h1 = __float2bfloat16(v.y);
                __nv_bfloat16 h2 = __float2bfloat16(v.z), h3 = __float2bfloat16(v.w);
                __nv_bfloat16 l0 = __float2bfloat16(v.x - __bfloat162float(h0));
                __nv_bfloat16 l1 = __float2bfloat16(v.y - __bfloat162float(h1));
                __nv_bfloat16 l2 = __float2bfloat16(v.z - __bfloat162float(h2));
                __nv_bfloat16 l3 = __float2bfloat16(v.w - __bfloat162float(h3));
                uint2 hw = make_uint2(
                    (uint32_t)__bfloat16_as_ushort(h0) | ((uint32_t)__bfloat16_as_ushort(h1) << 16),
                    (uint32_t)__bfloat16_as_ushort(h2) | ((uint32_t)__bfloat16_as_ushort(h3) << 16));
                uint2 lw = make_uint2(
                    (uint32_t)__bfloat16_as_ushort(l0) | ((uint32_t)__bfloat16_as_ushort(l1) << 16),
                    (uint32_t)__bfloat16_as_ushort(l2) | ((uint32_t)__bfloat16_as_ushort(l3) << 16));
                *(uint2*)(ah + h * 4) = hw;
                *(uint2*)(al + h * 4) = lw;
            }
        }
        __pipeline_wait_prior(0);   // B(c) arrived (only outstanding commit)
        __syncthreads();

        // prefetch chunk c+1 into regs + alternate B stage (hidden under MMAs)
        if (c < 15) {
            int kbase = (c + 1) * 32 + aseg * 16;
            #pragma unroll
            for (int h = 0; h < 4; h++) {
                int gk = kbase + h * 4;
                areg[h] = make_float4(0.f, 0.f, 0.f, 0.f);
                if (rvalid && gk < IN_DIM) areg[h] = *(const float4*)(xrow + gk);
            }
            size_t off = (size_t)((c + 1) * 32 + bk) * HID_DIM + bn0;
            __nv_bfloat16* bh = Bh + (s ^ 1) * 4352 + bk * 136 + bn0;
            __nv_bfloat16* bl = Bl + (s ^ 1) * 4352 + bk * 136 + bn0;
            __pipeline_memcpy_async(bh,     g_w1hi + off,     16);
            __pipeline_memcpy_async(bh + 8, g_w1hi + off + 8, 16);
            __pipeline_memcpy_async(bl,     g_w1lo + off,     16);
            __pipeline_memcpy_async(bl + 8, g_w1lo + off + 8, 16);
            __pipeline_commit();
        }

        #pragma unroll
        for (int ks = 0; ks < 2; ks++) {
            wmma::fragment<wmma::matrix_a, 16, 16, 16, __nv_bfloat16, wmma::row_major> ah[2], al[2];
            #pragma unroll
            for (int i = 0; i < 2; i++) {
                wmma::load_matrix_sync(ah[i], Ah + s * 5120 + (warp_m * 32 + i * 16) * 40 + ks * 16, 40);
                wmma::load_matrix_sync(al[i], Al + s * 5120 + (warp_m * 32 + i * 16) * 40 + ks * 16, 40);
            }
            #pragma unroll
            for (int j = 0; j < 4; j++) {
                wmma::fragment<wmma::matrix_b, 16, 16, 16, __nv_bfloat16, wmma::row_major> bh, bl;
                int col = warp_n * 64 + j * 16;
                wmma::load_matrix_sync(bh, Bh + s * 4352 + ks * 16 * 136 + col, 136);
                wmma::load_matrix_sync(bl, Bl + s * 4352 + ks * 16 * 136 + col, 136);
                #pragma unroll
                for (int i = 0; i < 2; i++) {
                    wmma::mma_sync(acc[i][j], ah[i], bh, acc[i][j]);
                    wmma::mma_sync(acc[i][j], ah[i], bl, acc[i][j]);
                    wmma::mma_sync(acc[i][j], al[i], bh, acc[i][j]);
                }
            }
        }
        // no second barrier: next iter writes the other stage
    }

    #pragma unroll
    for (int i = 0; i < 2; i++)
        #pragma unroll
        for (int j = 0; j < 4; j++) {
            size_t off = (size_t)(row0 + warp_m * 32 + i * 16) * HID_DIM + warp_n * 64 + j * 16;
            wmma::store_matrix_sync(&g_h1[off], acc[i][j], HID_DIM, wmma::mem_row_major);
        }
}

// ---------------- preprocessing ----------------
__global__ void k_init() {
    int i = blockIdx.x * 256 + threadIdx.x;
    if (i < N_NODES) { g_deg[i] = 0; g_cursor[i] = 0; }
}
__global__ void k_degree(const void* __restrict__ ei) {
    int e = blockIdx.x * 256 + threadIdx.x;
    if (e >= N_EDGES) return;
    int d = edge_id(ei, (size_t)N_EDGES + e);
    if ((unsigned)d < N_NODES) atomicAdd(&g_deg[d], 1);
}
__global__ void k_dinv() {
    int i = blockIdx.x * 256 + threadIdx.x;
    if (i < N_NODES) g_dinv[i] = rsqrtf((float)(g_deg[i] + 1));
}
__global__ __launch_bounds__(1024) void k_scan1() {
    __shared__ int wsum[32];
    int t = threadIdx.x, lane = t & 31, w = t >> 5;
    int idx = blockIdx.x * 1024 + t;
    int v = (idx < N_NODES) ? g_deg[idx] : 0;
    int x = v;
    #pragma unroll
    for (int d = 1; d < 32; d <<= 1) {
        int y = __shfl_up_sync(0xffffffffu, x, d);
        if (lane >= d) x += y;
    }
    if (lane == 31) wsum[w] = x;
    __syncthreads();
    if (w == 0) {
        int s = wsum[lane];
        #pragma unroll
        for (int d = 1; d < 32; d <<= 1) {
            int y = __shfl_up_sync(0xffffffffu, s, d);
            if (lane >= d) s += y;
        }
        wsum[lane] = s;
    }
    __syncthreads();
    int woff = w ? wsum[w - 1] : 0;
    if (idx < N_NODES) g_rowptr[idx] = woff + x - v;
    if (t == 1023) g_bsum[blockIdx.x] = wsum[31];
}
__global__ void k_scan2(int nb) {
    __shared__ int ws[4];
    __shared__ int tot;
    int t = threadIdx.x, lane = t & 31, w = t >> 5;
    int v = (t < nb) ? g_bsum[t] : 0;
    int x = v;
    #pragma unroll
    for (int d = 1; d < 32; d <<= 1) {
        int y = __shfl_up_sync(0xffffffffu, x, d);
        if (lane >= d) x += y;
    }
    if (lane == 31) ws[w] = x;
    __syncthreads();
    if (t == 0) {
        int s = 0;
        #pragma unroll
        for (int i = 0; i < 4; i++) { int tv = ws[i]; ws[i] = s; s += tv; }
        tot = s;
    }
    __syncthreads();
    if (t < nb) g_bsum[t] = ws[w] + x - v;
    if (t == 0) g_rowptr[N_NODES] = tot;
}
__global__ void k_scan3() {
    int idx = blockIdx.x * 256 + threadIdx.x;
    if (idx < N_NODES) g_rowptr[idx] += g_bsum[idx >> 10];
}
__global__ void k_scatter(const void* __restrict__ ei) {
    int e = blockIdx.x * 256 + threadIdx.x;
    if (e >= N_EDGES) return;
    int s = edge_id(ei, e);
    int d = edge_id(ei, (size_t)N_EDGES + e);
    if ((unsigned)s >= N_NODES || (unsigned)d >= N_NODES) return;
    int p = g_rowptr[d] + atomicAdd(&g_cursor[d], 1);
    g_csr_src[p] = s;
}

// ---------------- aggregation 1: relu(agg + b1), writes bf16 hi/lo ----------------
__global__ __launch_bounds__(256) void k_agg1(const float* __restrict__ b1) {
    int node = blockIdx.x * 8 + (threadIdx.x >> 5);
    if (node >= N_NODES) return;
    int lane = threadIdx.x & 31;
    const float4* h = (const float4*)g_h1;

    float dn = g_dinv[node];
    float4 acc = h[(size_t)node * 32 + lane];
    acc.x *= dn; acc.y *= dn; acc.z *= dn; acc.w *= dn;

    int p0 = g_rowptr[node], p1 = g_rowptr[node + 1];
    for (int p = p0; p < p1; p++) {
        int s  = g_csr_src[p];
        float w = g_dinv[s];
        float4 v = h[(size_t)s * 32 + lane];
        acc.x += w * v.x; acc.y += w * v.y; acc.z += w * v.z; acc.w += w * v.w;
    }
    float4 bb = ((const float4*)b1)[lane];
    float4 o;
    o.x = fmaxf(fmaf(dn, acc.x, bb.x), 0.f);
    o.y = fmaxf(fmaf(dn, acc.y, bb.y), 0.f);
    o.z = fmaxf(fmaf(dn, acc.z, bb.z), 0.f);
    o.w = fmaxf(fmaf(dn, acc.w, bb.w), 0.f);

    __nv_bfloat16 h0 = __float2bfloat16(o.x), h1v = __float2bfloat16(o.y);
    __nv_bfloat16 h2 = __float2bfloat16(o.z), h3 = __float2bfloat16(o.w);
    __nv_bfloat16 l0 = __float2bfloat16(o.x - __bfloat162float(h0));
    __nv_bfloat16 l1 = __float2bfloat16(o.y - __bfloat162float(h1v));
    __nv_bfloat16 l2 = __float2bfloat16(o.z - __bfloat162float(h2));
    __nv_bfloat16 l3 = __float2bfloat16(o.w - __bfloat162float(h3));
    uint2 hw = make_uint2(
        (uint32_t)__bfloat16_as_ushort(h0) | ((uint32_t)__bfloat16_as_ushort(h1v) << 16),
        (uint32_t)__bfloat16_as_ushort(h2) | ((uint32_t)__bfloat16_as_ushort(h3) << 16));
    uint2 lw = make_uint2(
        (uint32_t)__bfloat16_as_ushort(l0) | ((uint32_t)__bfloat16_as_ushort(l1) << 16),
        (uint32_t)__bfloat16_as_ushort(l2) | ((uint32_t)__bfloat16_as_ushort(l3) << 16));
    *(uint2*)&g_a1hi[(size_t)node * HID_DIM + lane * 4] = hw;
    *(uint2*)&g_a1lo[(size_t)node * HID_DIM + lane * 4] = lw;
}

// ---------------- GEMM2: g_h2p = a1 @ W2, wmma bf16 3-term ----------------
__global__ __launch_bounds__(256) void k_gemm2_mma() {
    __shared__ __nv_bfloat16 Ah[128][40];
    __shared__ __nv_bfloat16 Al[128][40];
    __shared__ __nv_bfloat16 Bh[32][72];
    __shared__ __nv_bfloat16 Bl[32][72];

    int t = threadIdx.x;
    int wid = t >> 5;           // rows wid*16
    int row0 = blockIdx.x * 128;

    wmma::fragment<wmma::accumulator, 16, 16, 16, float> acc[4];
    #pragma unroll
    for (int j = 0; j < 4; j++) wmma::fill_fragment(acc[j], 0.f);

    int arow = t >> 1, aseg = t & 1;
    int bk = t >> 3, bn0 = (t & 7) << 3;

    for (int c = 0; c < 4; c++) {
        {
            size_t aoff = (size_t)(row0 + arow) * HID_DIM + c * 32 + aseg * 16;
            __pipeline_memcpy_async(&Ah[arow][aseg * 16],     g_a1hi + aoff,     16);
            __pipeline_memcpy_async(&Ah[arow][aseg * 16 + 8], g_a1hi + aoff + 8, 16);
            __pipeline_memcpy_async(&Al[arow][aseg * 16],     g_a1lo + aoff,     16);
            __pipeline_memcpy_async(&Al[arow][aseg * 16 + 8], g_a1lo + aoff + 8, 16);
            size_t boff = (size_t)(c * 32 + bk) * OUT_PAD + bn0;
            __pipeline_memcpy_async(&Bh[bk][bn0], g_w2hi + boff, 16);
            __pipeline_memcpy_async(&Bl[bk][bn0], g_w2lo + boff, 16);
            __pipeline_commit();
        }
        __pipeline_wait_prior(0);
        __syncthreads();

        #pragma unroll
        for (int ks = 0; ks < 2; ks++) {
            wmma::fragment<wmma::matrix_a, 16, 16, 16, __nv_bfloat16, wmma::row_major> ah, al;
            wmma::load_matrix_sync(ah, &Ah[wid * 16][ks * 16], 40);
            wmma::load_matrix_sync(al, &Al[wid * 16][ks * 16], 40);
            #pragma unroll
            for (int j = 0; j < 4; j++) {
                wmma::fragment<wmma::matrix_b, 16, 16, 16, __nv_bfloat16, wmma::row_major> bh, bl;
                wmma::load_matrix_sync(bh, &Bh[ks * 16][j * 16], 72);
                wmma::load_matrix_sync(bl, &Bl[ks * 16][j * 16], 72);
                wmma::mma_sync(acc[j], ah, bh, acc[j]);
                wmma::mma_sync(acc[j], ah, bl, acc[j]);
                wmma::mma_sync(acc[j], al, bh, acc[j]);
            }
        }
        __syncthreads();
    }

    #pragma unroll
    for (int j = 0; j < 4; j++) {
        size_t off = (size_t)(row0 + wid * 16) * OUT_PAD + j * 16;
        wmma::store_matrix_sync(&g_h2p[off], acc[j], OUT_PAD, wmma::mem_row_major);
    }
}

// ---------------- aggregation 2 + bias + log_softmax ----------------
__global__ __launch_bounds__(256) void k_agg2(const float* __restrict__ b2,
                                              float* __restrict__ out) {
    int node = blockIdx.x * 8 + (threadIdx.x >> 5);
    if (node >= N_NODES) return;
    int lane = threadIdx.x & 31;

    float dn = g_dinv[node];
    float acc0, acc1 = 0.f;
    {
        size_t b = (size_t)node * OUT_PAD;
        acc0 = dn * g_h2p[b + lane];
        if (lane < 8) acc1 = dn * g_h2p[b + 32 + lane];
    }
    int p0 = g_rowptr[node], p1 = g_rowptr[node + 1];
    for (int p = p0; p < p1; p++) {
        int s  = g_csr_src[p];
        float w = g_dinv[s];
        size_t b = (size_t)s * OUT_PAD;
        acc0 += w * g_h2p[b + lane];
        if (lane < 8) acc1 += w * g_h2p[b + 32 + lane];
    }
    acc0 = fmaf(dn, acc0, b2[lane]);
    if (lane < 8) acc1 = fmaf(dn, acc1, b2[32 + lane]);

    float m = acc0;
    if (lane < 8) m = fmaxf(m, acc1);
    #pragma unroll
    for (int o = 16; o; o >>= 1) m = fmaxf(m, __shfl_xor_sync(0xffffffffu, m, o));
    float s = __expf(acc0 - m) + ((lane < 8) ? __expf(acc1 - m) : 0.f);
    #pragma unroll
    for (int o = 16; o; o >>= 1) s += __shfl_xor_sync(0xffffffffu, s, o);
    float ls = __logf(s);

    out[(size_t)node * OUT_DIM + lane] = acc0 - m - ls;
    if (lane < 8) out[(size_t)node * OUT_DIM + 32 + lane] = acc1 - m - ls;
}

// ---------------- launch ----------------
extern "C" void kernel_launch(void* const* d_in, const int* in_sizes, int n_in,
                              void* d_out, int out_size) {
    const float* x  = (const float*)d_in[0];
    const void*  ei = d_in[1];
    const float* W1 = (const float*)d_in[2];
    const float* b1 = (const float*)d_in[3];
    const float* W2 = (const float*)d_in[4];
    const float* b2 = (const float*)d_in[5];
    float*       out = (float*)d_out;

    const int TB = 256;
    int nb_nodes = (N_NODES + TB - 1) / TB;
    int nb_edges = (N_EDGES + TB - 1) / TB;
    int nb_scan  = (N_NODES + 1023) / 1024;   // 98

    static int smem_set = 0;
    if (!smem_set) {
        cudaFuncSetAttribute(k_gemm1_mma, cudaFuncAttributeMaxDynamicSharedMemorySize, G1_SMEM_BYTES);
        smem_set = 1;
    }

    // Order keeps k_gemm1_mma at ncu's captured slot (launch index 3).
    k_detect<<<1, 1>>>(ei);                          // 0
    k_wsplit<<<(K_PAD * HID_DIM) / TB, TB>>>(W1);    // 1
    k_w2split<<<(HID_DIM * OUT_PAD) / TB, TB>>>(W2); // 2
    k_gemm1_mma<<<N_PAD / 128, 256, G1_SMEM_BYTES>>>(x); // 3 <- profiled
    k_init<<<nb_nodes, TB>>>();                      // 4
    k_degree<<<nb_edges, TB>>>(ei);                  // 5
    k_dinv<<<nb_nodes, TB>>>();                      // 6
    k_scan1<<<nb_scan, 1024>>>();
    k_scan2<<<1, 128>>>(nb_scan);
    k_scan3<<<nb_nodes, TB>>>();
    k_scatter<<<nb_edges, TB>>>(ei);
    k_agg1<<<(N_NODES + 7) / 8, 256>>>(b1);
    k_gemm2_mma<<<N_PAD / 128, 256>>>();
    k_agg2<<<(N_NODES + 7) / 8, 256>>>(b2, out);
}

// round 13
// speedup vs baseline: 2.4784x; 1.1167x over previous
#include <cuda_runtime.h>
#include <cuda_bf16.h>
#include <cuda_pipeline_primitives.h>
#include <mma.h>
#include <math.h>
#include <stdint.h>

using namespace nvcuda;

#define N_NODES 100000
#define N_PAD   100096          // 782 * 128
#define N_EDGES 1600000
#define IN_DIM  500
#define HID_DIM 128
#define OUT_DIM 40
#define OUT_PAD 64
#define K_PAD   512

// ---------------- scratch ----------------
__device__ int   g_is64;
__device__ __align__(256) int   g_deg[N_NODES];
__device__ __align__(256) int   g_cursor[N_NODES];
__device__ __align__(256) float g_dinv[N_NODES];
__device__ __align__(256) int   g_rowptr[N_NODES + 1];
__device__ __align__(256) int   g_bsum[128];
__device__ __align__(256) int   g_csr_src[N_EDGES];
__device__ __align__(256) __nv_bfloat16 g_w1hi[K_PAD * HID_DIM];   // [k][n]
__device__ __align__(256) __nv_bfloat16 g_w1lo[K_PAD * HID_DIM];
__device__ __align__(256) __nv_bfloat16 g_w2hi[HID_DIM * OUT_PAD]; // [k][n] padded
__device__ __align__(256) __nv_bfloat16 g_w2lo[HID_DIM * OUT_PAD];
__device__ __align__(256) float g_h1[(size_t)N_PAD * HID_DIM];
__device__ __align__(256) __nv_bfloat16 g_a1hi[(size_t)N_PAD * HID_DIM];
__device__ __align__(256) __nv_bfloat16 g_a1lo[(size_t)N_PAD * HID_DIM];
__device__ __align__(256) float g_h2p[(size_t)N_PAD * OUT_PAD];

// ---------------- edge decode ----------------
__device__ __forceinline__ int edge_id(const void* ei, size_t idx) {
    if (g_is64) return (int)((const long long*)ei)[idx];
    return ((const int*)ei)[idx];
}
__global__ void k_detect(const void* ei) {
    const long long* p = (const long long*)ei;
    int is64 = 1;
    for (int i = 0; i < 16; i++) {
        long long v = p[i];
        if (v < 0 || v >= N_NODES) { is64 = 0; break; }
    }
    g_is64 = is64;
}

// ---------------- weight splits ----------------
__global__ void k_wsplit(const float* __restrict__ W1) {
    int idx = blockIdx.x * 256 + threadIdx.x;     // 65536 = 512*128
    int k = idx >> 7, n = idx & 127;
    float v = (k < IN_DIM) ? W1[(size_t)k * HID_DIM + n] : 0.f;
    __nv_bfloat16 h = __float2bfloat16(v);
    g_w1hi[idx] = h;
    g_w1lo[idx] = __float2bfloat16(v - __bfloat162float(h));
}
__global__ void k_w2split(const float* __restrict__ W2) {
    int idx = blockIdx.x * 256 + threadIdx.x;     // 8192 = 128*64
    int k = idx >> 6, n = idx & 63;
    float v = (n < OUT_DIM) ? W2[(size_t)k * OUT_DIM + n] : 0.f;
    __nv_bfloat16 h = __float2bfloat16(v);
    g_w2hi[idx] = h;
    g_w2lo[idx] = __float2bfloat16(v - __bfloat162float(h));
}

// ---------------- GEMM1: g_h1 = x @ W1, wmma bf16 3-term, 2-stage pipeline ----------------
// Dynamic smem layout (bf16 elems):
//   Ah[2][128][40] @ 0       Al[2][128][40] @ 10240
//   Bh[2][32][136] @ 20480   Bl[2][32][136] @ 29184
#define G1_SMEM_BYTES ((20480 + 2 * 8704) * 2)   // 75776 B

__global__ __launch_bounds__(256, 2) void k_gemm1_mma(const float* __restrict__ X) {
    extern __shared__ __nv_bfloat16 sm[];
    __nv_bfloat16* Ah = sm;
    __nv_bfloat16* Al = sm + 10240;
    __nv_bfloat16* Bh = sm + 20480;
    __nv_bfloat16* Bl = sm + 20480 + 8704;

    int t = threadIdx.x;
    int wid = t >> 5;
    int warp_m = wid & 3;       // rows warp_m*32
    int warp_n = wid >> 2;      // cols warp_n*64
    int row0 = blockIdx.x * 128;

    wmma::fragment<wmma::accumulator, 16, 16, 16, float> acc[2][4];
    #pragma unroll
    for (int i = 0; i < 2; i++)
        #pragma unroll
        for (int j = 0; j < 4; j++) wmma::fill_fragment(acc[i][j], 0.f);

    int arow = t >> 1, aseg = t & 1;                 // A: row, 16-wide k segment
    const float* xrow = X + (size_t)(row0 + arow) * IN_DIM;
    bool rvalid = (row0 + arow) < N_NODES;
    int bk = t >> 3, bn0 = (t & 7) << 4;             // B: k row (0..31), 16-wide n seg

    float4 areg[4];

    // prefetch chunk 0
    {
        int kbase = aseg * 16;
        #pragma unroll
        for (int h = 0; h < 4; h++) {
            int gk = kbase + h * 4;
            areg[h] = make_float4(0.f, 0.f, 0.f, 0.f);
            if (rvalid && gk < IN_DIM) areg[h] = *(const float4*)(xrow + gk);
        }
        size_t off = (size_t)bk * HID_DIM + bn0;
        __nv_bfloat16* bh = Bh + bk * 136 + bn0;
        __nv_bfloat16* bl = Bl + bk * 136 + bn0;
        __pipeline_memcpy_async(bh,     g_w1hi + off,     16);
        __pipeline_memcpy_async(bh + 8, g_w1hi + off + 8, 16);
        __pipeline_memcpy_async(bl,     g_w1lo + off,     16);
        __pipeline_memcpy_async(bl + 8, g_w1lo + off + 8, 16);
        __pipeline_commit();
    }

    for (int c = 0; c < 16; c++) {
        int s = c & 1;
        // convert prefetched A regs -> stage s
        {
            __nv_bfloat16* ah = Ah + s * 5120 + arow * 40 + aseg * 16;
            __nv_bfloat16* al = Al + s * 5120 + arow * 40 + aseg * 16;
            #pragma unroll
            for (int h = 0; h < 4; h++) {
                float4 v = areg[h];
                __nv_bfloat16 h0 = __float2bfloat16(v.x), h1 = __float2bfloat16(v.y);
                __nv_bfloat16 h2 = __float2bfloat16(v.z), h3 = __float2bfloat16(v.w);
                __nv_bfloat16 l0 = __float2bfloat16(v.x - __bfloat162float(h0));
                __nv_bfloat16 l1 = __float2bfloat16(v.y - __bfloat162float(h1));
                __nv_bfloat16 l2 = __float2bfloat16(v.z - __bfloat162float(h2));
                __nv_bfloat16 l3 = __float2bfloat16(v.w - __bfloat162float(h3));
                uint2 hw = make_uint2(
                    (uint32_t)__bfloat16_as_ushort(h0) | ((uint32_t)__bfloat16_as_ushort(h1) << 16),
                    (uint32_t)__bfloat16_as_ushort(h2) | ((uint32_t)__bfloat16_as_ushort(h3) << 16));
                uint2 lw = make_uint2(
                    (uint32_t)__bfloat16_as_ushort(l0) | ((uint32_t)__bfloat16_as_ushort(l1) << 16),
                    (uint32_t)__bfloat16_as_ushort(l2) | ((uint32_t)__bfloat16_as_ushort(l3) << 16));
                *(uint2*)(ah + h * 4) = hw;
                *(uint2*)(al + h * 4) = lw;
            }
        }
        __pipeline_wait_prior(0);   // B(c) arrived (only outstanding commit)
        __syncthreads();

        // prefetch chunk c+1 into regs + alternate B stage (hidden under MMAs)
        if (c < 15) {
            int kbase = (c + 1) * 32 + aseg * 16;
            #pragma unroll
            for (int h = 0; h < 4; h++) {
                int gk = kbase + h * 4;
                areg[h] = make_float4(0.f, 0.f, 0.f, 0.f);
                if (rvalid && gk < IN_DIM) areg[h] = *(const float4*)(xrow + gk);
            }
            size_t off = (size_t)((c + 1) * 32 + bk) * HID_DIM + bn0;
            __nv_bfloat16* bh = Bh + (s ^ 1) * 4352 + bk * 136 + bn0;
            __nv_bfloat16* bl = Bl + (s ^ 1) * 4352 + bk * 136 + bn0;
            __pipeline_memcpy_async(bh,     g_w1hi + off,     16);
            __pipeline_memcpy_async(bh + 8, g_w1hi + off + 8, 16);
            __pipeline_memcpy_async(bl,     g_w1lo + off,     16);
            __pipeline_memcpy_async(bl + 8, g_w1lo + off + 8, 16);
            __pipeline_commit();
        }

        #pragma unroll
        for (int ks = 0; ks < 2; ks++) {
            wmma::fragment<wmma::matrix_a, 16, 16, 16, __nv_bfloat16, wmma::row_major> ah[2], al[2];
            #pragma unroll
            for (int i = 0; i < 2; i++) {
                wmma::load_matrix_sync(ah[i], Ah + s * 5120 + (warp_m * 32 + i * 16) * 40 + ks * 16, 40);
                wmma::load_matrix_sync(al[i], Al + s * 5120 + (warp_m * 32 + i * 16) * 40 + ks * 16, 40);
            }
            #pragma unroll
            for (int j = 0; j < 4; j++) {
                wmma::fragment<wmma::matrix_b, 16, 16, 16, __nv_bfloat16, wmma::row_major> bh, bl;
                int col = warp_n * 64 + j * 16;
                wmma::load_matrix_sync(bh, Bh + s * 4352 + ks * 16 * 136 + col, 136);
                wmma::load_matrix_sync(bl, Bl + s * 4352 + ks * 16 * 136 + col, 136);
                #pragma unroll
                for (int i = 0; i < 2; i++) {
                    wmma::mma_sync(acc[i][j], ah[i], bh, acc[i][j]);
                    wmma::mma_sync(acc[i][j], ah[i], bl, acc[i][j]);
                    wmma::mma_sync(acc[i][j], al[i], bh, acc[i][j]);
                }
            }
        }
        // no second barrier: next iter writes the other stage
    }

    #pragma unroll
    for (int i = 0; i < 2; i++)
        #pragma unroll
        for (int j = 0; j < 4; j++) {
            size_t off = (size_t)(row0 + warp_m * 32 + i * 16) * HID_DIM + warp_n * 64 + j * 16;
            wmma::store_matrix_sync(&g_h1[off], acc[i][j], HID_DIM, wmma::mem_row_major);
        }
}

// ---------------- preprocessing ----------------
__global__ void k_init() {
    int i = blockIdx.x * 256 + threadIdx.x;
    if (i < N_NODES) { g_deg[i] = 0; g_cursor[i] = 0; }
}
__global__ void k_degree(const void* __restrict__ ei) {
    int e = blockIdx.x * 256 + threadIdx.x;
    if (e >= N_EDGES) return;
    int d = edge_id(ei, (size_t)N_EDGES + e);
    if ((unsigned)d < N_NODES) atomicAdd(&g_deg[d], 1);
}
__global__ void k_dinv() {
    int i = blockIdx.x * 256 + threadIdx.x;
    if (i < N_NODES) g_dinv[i] = rsqrtf((float)(g_deg[i] + 1));
}
__global__ __launch_bounds__(1024) void k_scan1() {
    __shared__ int wsum[32];
    int t = threadIdx.x, lane = t & 31, w = t >> 5;
    int idx = blockIdx.x * 1024 + t;
    int v = (idx < N_NODES) ? g_deg[idx] : 0;
    int x = v;
    #pragma unroll
    for (int d = 1; d < 32; d <<= 1) {
        int y = __shfl_up_sync(0xffffffffu, x, d);
        if (lane >= d) x += y;
    }
    if (lane == 31) wsum[w] = x;
    __syncthreads();
    if (w == 0) {
        int s = wsum[lane];
        #pragma unroll
        for (int d = 1; d < 32; d <<= 1) {
            int y = __shfl_up_sync(0xffffffffu, s, d);
            if (lane >= d) s += y;
        }
        wsum[lane] = s;
    }
    __syncthreads();
    int woff = w ? wsum[w - 1] : 0;
    if (idx < N_NODES) g_rowptr[idx] = woff + x - v;
    if (t == 1023) g_bsum[blockIdx.x] = wsum[31];
}
__global__ void k_scan2(int nb) {
    __shared__ int ws[4];
    __shared__ int tot;
    int t = threadIdx.x, lane = t & 31, w = t >> 5;
    int v = (t < nb) ? g_bsum[t] : 0;
    int x = v;
    #pragma unroll
    for (int d = 1; d < 32; d <<= 1) {
        int y = __shfl_up_sync(0xffffffffu, x, d);
        if (lane >= d) x += y;
    }
    if (lane == 31) ws[w] = x;
    __syncthreads();
    if (t == 0) {
        int s = 0;
        #pragma unroll
        for (int i = 0; i < 4; i++) { int tv = ws[i]; ws[i] = s; s += tv; }
        tot = s;
    }
    __syncthreads();
    if (t < nb) g_bsum[t] = ws[w] + x - v;
    if (t == 0) g_rowptr[N_NODES] = tot;
}
__global__ void k_scan3() {
    int idx = blockIdx.x * 256 + threadIdx.x;
    if (idx < N_NODES) g_rowptr[idx] += g_bsum[idx >> 10];
}
__global__ void k_scatter(const void* __restrict__ ei) {
    int e = blockIdx.x * 256 + threadIdx.x;
    if (e >= N_EDGES) return;
    int s = edge_id(ei, e);
    int d = edge_id(ei, (size_t)N_EDGES + e);
    if ((unsigned)s >= N_NODES || (unsigned)d >= N_NODES) return;
    int p = g_rowptr[d] + atomicAdd(&g_cursor[d], 1);
    g_csr_src[p] = s;
}

// ---------------- aggregation 1: relu(agg + b1), writes bf16 hi/lo ----------------
__global__ __launch_bounds__(256) void k_agg1(const float* __restrict__ b1) {
    int node = blockIdx.x * 8 + (threadIdx.x >> 5);
    if (node >= N_NODES) return;
    int lane = threadIdx.x & 31;
    const float4* h = (const float4*)g_h1;

    float dn = g_dinv[node];
    float4 acc = h[(size_t)node * 32 + lane];
    acc.x *= dn; acc.y *= dn; acc.z *= dn; acc.w *= dn;

    int p0 = g_rowptr[node], p1 = g_rowptr[node + 1];
    for (int p = p0; p < p1; p++) {
        int s  = g_csr_src[p];
        float w = g_dinv[s];
        float4 v = h[(size_t)s * 32 + lane];
        acc.x += w * v.x; acc.y += w * v.y; acc.z += w * v.z; acc.w += w * v.w;
    }
    float4 bb = ((const float4*)b1)[lane];
    float4 o;
    o.x = fmaxf(fmaf(dn, acc.x, bb.x), 0.f);
    o.y = fmaxf(fmaf(dn, acc.y, bb.y), 0.f);
    o.z = fmaxf(fmaf(dn, acc.z, bb.z), 0.f);
    o.w = fmaxf(fmaf(dn, acc.w, bb.w), 0.f);

    __nv_bfloat16 h0 = __float2bfloat16(o.x), h1v = __float2bfloat16(o.y);
    __nv_bfloat16 h2 = __float2bfloat16(o.z), h3 = __float2bfloat16(o.w);
    __nv_bfloat16 l0 = __float2bfloat16(o.x - __bfloat162float(h0));
    __nv_bfloat16 l1 = __float2bfloat16(o.y - __bfloat162float(h1v));
    __nv_bfloat16 l2 = __float2bfloat16(o.z - __bfloat162float(h2));
    __nv_bfloat16 l3 = __float2bfloat16(o.w - __bfloat162float(h3));
    uint2 hw = make_uint2(
        (uint32_t)__bfloat16_as_ushort(h0) | ((uint32_t)__bfloat16_as_ushort(h1v) << 16),
        (uint32_t)__bfloat16_as_ushort(h2) | ((uint32_t)__bfloat16_as_ushort(h3) << 16));
    uint2 lw = make_uint2(
        (uint32_t)__bfloat16_as_ushort(l0) | ((uint32_t)__bfloat16_as_ushort(l1) << 16),
        (uint32_t)__bfloat16_as_ushort(l2) | ((uint32_t)__bfloat16_as_ushort(l3) << 16));
    *(uint2*)&g_a1hi[(size_t)node * HID_DIM + lane * 4] = hw;
    *(uint2*)&g_a1lo[(size_t)node * HID_DIM + lane * 4] = lw;
}

// ---------------- GEMM2: g_h2p = a1 @ W2, wmma bf16 3-term ----------------
__global__ __launch_bounds__(256, 2) void k_gemm2_mma() {
    __shared__ __nv_bfloat16 Ah[128][40];
    __shared__ __nv_bfloat16 Al[128][40];
    __shared__ __nv_bfloat16 Bh[32][72];
    __shared__ __nv_bfloat16 Bl[32][72];

    int t = threadIdx.x;
    int wid = t >> 5;           // rows wid*16
    int row0 = blockIdx.x * 128;

    wmma::fragment<wmma::accumulator, 16, 16, 16, float> acc[4];
    #pragma unroll
    for (int j = 0; j < 4; j++) wmma::fill_fragment(acc[j], 0.f);

    int arow = t >> 1, aseg = t & 1;
    int bk = t >> 3, bn0 = (t & 7) << 3;

    for (int c = 0; c < 4; c++) {
        {
            size_t aoff = (size_t)(row0 + arow) * HID_DIM + c * 32 + aseg * 16;
            __pipeline_memcpy_async(&Ah[arow][aseg * 16],     g_a1hi + aoff,     16);
            __pipeline_memcpy_async(&Ah[arow][aseg * 16 + 8], g_a1hi + aoff + 8, 16);
            __pipeline_memcpy_async(&Al[arow][aseg * 16],     g_a1lo + aoff,     16);
            __pipeline_memcpy_async(&Al[arow][aseg * 16 + 8], g_a1lo + aoff + 8, 16);
            size_t boff = (size_t)(c * 32 + bk) * OUT_PAD + bn0;
            __pipeline_memcpy_async(&Bh[bk][bn0], g_w2hi + boff, 16);
            __pipeline_memcpy_async(&Bl[bk][bn0], g_w2lo + boff, 16);
            __pipeline_commit();
        }
        __pipeline_wait_prior(0);
        __syncthreads();

        #pragma unroll
        for (int ks = 0; ks < 2; ks++) {
            wmma::fragment<wmma::matrix_a, 16, 16, 16, __nv_bfloat16, wmma::row_major> ah, al;
            wmma::load_matrix_sync(ah, &Ah[wid * 16][ks * 16], 40);
            wmma::load_matrix_sync(al, &Al[wid * 16][ks * 16], 40);
            #pragma unroll
            for (int j = 0; j < 4; j++) {
                wmma::fragment<wmma::matrix_b, 16, 16, 16, __nv_bfloat16, wmma::row_major> bh, bl;
                wmma::load_matrix_sync(bh, &Bh[ks * 16][j * 16], 72);
                wmma::load_matrix_sync(bl, &Bl[ks * 16][j * 16], 72);
                wmma::mma_sync(acc[j], ah, bh, acc[j]);
                wmma::mma_sync(acc[j], ah, bl, acc[j]);
                wmma::mma_sync(acc[j], al, bh, acc[j]);
            }
        }
        __syncthreads();
    }

    #pragma unroll
    for (int j = 0; j < 4; j++) {
        size_t off = (size_t)(row0 + wid * 16) * OUT_PAD + j * 16;
        wmma::store_matrix_sync(&g_h2p[off], acc[j], OUT_PAD, wmma::mem_row_major);
    }
}

// ---------------- aggregation 2 + bias + log_softmax ----------------
__global__ __launch_bounds__(256) void k_agg2(const float* __restrict__ b2,
                                              float* __restrict__ out) {
    int node = blockIdx.x * 8 + (threadIdx.x >> 5);
    if (node >= N_NODES) return;
    int lane = threadIdx.x & 31;

    float dn = g_dinv[node];
    float acc0, acc1 = 0.f;
    {
        size_t b = (size_t)node * OUT_PAD;
        acc0 = dn * g_h2p[b + lane];
        if (lane < 8) acc1 = dn * g_h2p[b + 32 + lane];
    }
    int p0 = g_rowptr[node], p1 = g_rowptr[node + 1];
    for (int p = p0; p < p1; p++) {
        int s  = g_csr_src[p];
        float w = g_dinv[s];
        size_t b = (size_t)s * OUT_PAD;
        acc0 += w * g_h2p[b + lane];
        if (lane < 8) acc1 += w * g_h2p[b + 32 + lane];
    }
    acc0 = fmaf(dn, acc0, b2[lane]);
    if (lane < 8) acc1 = fmaf(dn, acc1, b2[32 + lane]);

    float m = acc0;
    if (lane < 8) m = fmaxf(m, acc1);
    #pragma unroll
    for (int o = 16; o; o >>= 1) m = fmaxf(m, __shfl_xor_sync(0xffffffffu, m, o));
    float s = __expf(acc0 - m) + ((lane < 8) ? __expf(acc1 - m) : 0.f);
    #pragma unroll
    for (int o = 16; o; o >>= 1) s += __shfl_xor_sync(0xffffffffu, s, o);
    float ls = __logf(s);

    out[(size_t)node * OUT_DIM + lane] = acc0 - m - ls;
    if (lane < 8) out[(size_t)node * OUT_DIM + 32 + lane] = acc1 - m - ls;
}

// ---------------- launch ----------------
extern "C" void kernel_launch(void* const* d_in, const int* in_sizes, int n_in,
                              void* d_out, int out_size) {
    const float* x  = (const float*)d_in[0];
    const void*  ei = d_in[1];
    const float* W1 = (const float*)d_in[2];
    const float* b1 = (const float*)d_in[3];
    const float* W2 = (const float*)d_in[4];
    const float* b2 = (const float*)d_in[5];
    float*       out = (float*)d_out;

    const int TB = 256;
    int nb_nodes = (N_NODES + TB - 1) / TB;
    int nb_edges = (N_EDGES + TB - 1) / TB;
    int nb_scan  = (N_NODES + 1023) / 1024;   // 98

    static int smem_set = 0;
    if (!smem_set) {
        cudaFuncSetAttribute(k_gemm1_mma, cudaFuncAttributeMaxDynamicSharedMemorySize, G1_SMEM_BYTES);
        smem_set = 1;
    }

    // Order keeps k_gemm1_mma at ncu's captured slot (launch index 3).
    k_detect<<<1, 1>>>(ei);                          // 0
    k_wsplit<<<(K_PAD * HID_DIM) / TB, TB>>>(W1);    // 1
    k_w2split<<<(HID_DIM * OUT_PAD) / TB, TB>>>(W2); // 2
    k_gemm1_mma<<<N_PAD / 128, 256, G1_SMEM_BYTES>>>(x); // 3 <- profiled
    k_init<<<nb_nodes, TB>>>();                      // 4
    k_degree<<<nb_edges, TB>>>(ei);                  // 5
    k_dinv<<<nb_nodes, TB>>>();                      // 6
    k_scan1<<<nb_scan, 1024>>>();
    k_scan2<<<1, 128>>>(nb_scan);
    k_scan3<<<nb_nodes, TB>>>();
    k_scatter<<<nb_edges, TB>>>(ei);
    k_agg1<<<(N_NODES + 7) / 8, 256>>>(b1);
    k_gemm2_mma<<<N_PAD / 128, 256>>>();
    k_agg2<<<(N_NODES + 7) / 8, 256>>>(b2, out);
}

// round 14
// speedup vs baseline: 2.6882x; 1.0847x over previous
#include <cuda_runtime.h>
#include <cuda_bf16.h>
#include <cuda_pipeline_primitives.h>
#include <mma.h>
#include <math.h>
#include <stdint.h>

using namespace nvcuda;

#define N_NODES 100000
#define N_PAD   100096          // 782 * 128
#define N_EDGES 1600000
#define IN_DIM  500
#define HID_DIM 128
#define OUT_DIM 40
#define OUT_PAD 64
#define K_PAD   512

// ---------------- scratch ----------------
__device__ int   g_is64;
__device__ __align__(256) int   g_deg[N_NODES];
__device__ __align__(256) int   g_cursor[N_NODES];
__device__ __align__(256) float g_dinv[N_NODES];
__device__ __align__(256) int   g_rowptr[N_NODES + 1];
__device__ __align__(256) int   g_bsum[128];
__device__ __align__(256) int   g_csr_src[N_EDGES];
__device__ __align__(256) __nv_bfloat16 g_w1hi[K_PAD * HID_DIM];   // [k][n]
__device__ __align__(256) __nv_bfloat16 g_w1lo[K_PAD * HID_DIM];
__device__ __align__(256) __nv_bfloat16 g_w2hi[HID_DIM * OUT_PAD]; // [k][n] padded
__device__ __align__(256) __nv_bfloat16 g_w2lo[HID_DIM * OUT_PAD];
__device__ __align__(256) float g_h1[(size_t)N_PAD * HID_DIM];
__device__ __align__(256) __nv_bfloat16 g_a1hi[(size_t)N_PAD * HID_DIM];
__device__ __align__(256) __nv_bfloat16 g_a1lo[(size_t)N_PAD * HID_DIM];
__device__ __align__(256) float g_h2p[(size_t)N_PAD * OUT_PAD];

// ---------------- mma helpers ----------------
__device__ __forceinline__ uint32_t pack_bf16_hi(float x, float y) {
    return (uint32_t)__bfloat16_as_ushort(__float2bfloat16(x)) |
           ((uint32_t)__bfloat16_as_ushort(__float2bfloat16(y)) << 16);
}
__device__ __forceinline__ float bf_res(float x) {
    return x - __bfloat162float(__float2bfloat16(x));
}
__device__ __forceinline__ void mma_bf16(float* d, const uint32_t* a, uint32_t b0, uint32_t b1) {
    asm volatile("mma.sync.aligned.m16n8k16.row.col.f32.bf16.bf16.f32 "
                 "{%0,%1,%2,%3}, {%4,%5,%6,%7}, {%8,%9}, {%0,%1,%2,%3};"
                 : "+f"(d[0]), "+f"(d[1]), "+f"(d[2]), "+f"(d[3])
                 : "r"(a[0]), "r"(a[1]), "r"(a[2]), "r"(a[3]), "r"(b0), "r"(b1));
}
__device__ __forceinline__ void ldsm4t(uint32_t& r0, uint32_t& r1, uint32_t& r2, uint32_t& r3,
                                       uint32_t addr) {
    asm volatile("ldmatrix.sync.aligned.m8n8.x4.trans.shared.b16 {%0,%1,%2,%3}, [%4];"
                 : "=r"(r0), "=r"(r1), "=r"(r2), "=r"(r3) : "r"(addr));
}

// ---------------- edge decode ----------------
__device__ __forceinline__ int edge_id(const void* ei, size_t idx) {
    if (g_is64) return (int)((const long long*)ei)[idx];
    return ((const int*)ei)[idx];
}
__global__ void k_detect(const void* ei) {
    const long long* p = (const long long*)ei;
    int is64 = 1;
    for (int i = 0; i < 16; i++) {
        long long v = p[i];
        if (v < 0 || v >= N_NODES) { is64 = 0; break; }
    }
    g_is64 = is64;
}

// ---------------- weight splits ----------------
__global__ void k_wsplit(const float* __restrict__ W1) {
    int idx = blockIdx.x * 256 + threadIdx.x;     // 65536 = 512*128
    int k = idx >> 7, n = idx & 127;
    float v = (k < IN_DIM) ? W1[(size_t)k * HID_DIM + n] : 0.f;
    __nv_bfloat16 h = __float2bfloat16(v);
    g_w1hi[idx] = h;
    g_w1lo[idx] = __float2bfloat16(v - __bfloat162float(h));
}
__global__ void k_w2split(const float* __restrict__ W2) {
    int idx = blockIdx.x * 256 + threadIdx.x;     // 8192 = 128*64
    int k = idx >> 6, n = idx & 63;
    float v = (n < OUT_DIM) ? W2[(size_t)k * OUT_DIM + n] : 0.f;
    __nv_bfloat16 h = __float2bfloat16(v);
    g_w2hi[idx] = h;
    g_w2lo[idx] = __float2bfloat16(v - __bfloat162float(h));
}

// ---------------- GEMM1: g_h1 = x @ W1, raw mma.sync, A in registers ----------------
// CTA 128x128, 8 warps: warp_m (32 rows) x warp_n (64 cols). K chunks of 32.
// B (weights) in smem [k][n] stride 136, double-buffered cp.async; read via ldmatrix.x4.trans.
__global__ __launch_bounds__(256, 2) void k_gemm1_mma(const float* __restrict__ X) {
    __shared__ __nv_bfloat16 Bh[2][32][136];
    __shared__ __nv_bfloat16 Bl[2][32][136];

    int t = threadIdx.x;
    int wid = t >> 5, lane = t & 31;
    int warp_m = wid & 3, warp_n = wid >> 2;
    int row0 = blockIdx.x * 128;
    int g = lane >> 2, tig = lane & 3;

    float acc[2][8][4];
    #pragma unroll
    for (int i = 0; i < 2; i++)
        #pragma unroll
        for (int j = 0; j < 8; j++)
            #pragma unroll
            for (int q = 0; q < 4; q++) acc[i][j][q] = 0.f;

    // A fragment source rows for this thread
    int rA = row0 + warp_m * 32 + g;          // i-tile i: rows rA+16i, rA+16i+8
    int bk = t >> 3, bn0 = (t & 7) << 4;      // B cp.async: k row, 16-wide n seg

    // ldmatrix per-lane address pieces: sel = lane>>3 (matrix 0..3), rr = lane&7
    int sel = lane >> 3, rr = lane & 7;
    uint32_t lm_off = (uint32_t)((((sel & 1) * 8 + rr) * 136 + (sel >> 1) * 8 + warp_n * 64) * 2);
    uint32_t bh_sh = (uint32_t)__cvta_generic_to_shared(&Bh[0][0][0]);
    uint32_t bl_sh = (uint32_t)__cvta_generic_to_shared(&Bl[0][0][0]);
    const uint32_t STAGE_B = 32 * 136 * 2;    // bytes per stage

    float2 areg[8];
    #define LOAD_A(kk)                                                             \
        {                                                                          \
            int k0 = (kk) + 2 * tig, k1 = (kk) + 2 * tig + 8;                      \
            _Pragma("unroll")                                                      \
            for (int i = 0; i < 2; i++) {                                          \
                int r0_ = rA + i * 16, r1_ = r0_ + 8;                              \
                areg[i*4+0] = (r0_ < N_NODES && k0 < IN_DIM) ? *(const float2*)(X + (size_t)r0_ * IN_DIM + k0) : make_float2(0.f, 0.f); \
                areg[i*4+1] = (r1_ < N_NODES && k0 < IN_DIM) ? *(const float2*)(X + (size_t)r1_ * IN_DIM + k0) : make_float2(0.f, 0.f); \
                areg[i*4+2] = (r0_ < N_NODES && k1 < IN_DIM) ? *(const float2*)(X + (size_t)r0_ * IN_DIM + k1) : make_float2(0.f, 0.f); \
                areg[i*4+3] = (r1_ < N_NODES && k1 < IN_DIM) ? *(const float2*)(X + (size_t)r1_ * IN_DIM + k1) : make_float2(0.f, 0.f); \
            }                                                                      \
        }

    // prologue: B chunk 0 -> stage 0, A regs for (c=0, ks=0)
    {
        size_t off = (size_t)bk * HID_DIM + bn0;
        __pipeline_memcpy_async(&Bh[0][bk][bn0],     g_w1hi + off,     16);
        __pipeline_memcpy_async(&Bh[0][bk][bn0 + 8], g_w1hi + off + 8, 16);
        __pipeline_memcpy_async(&Bl[0][bk][bn0],     g_w1lo + off,     16);
        __pipeline_memcpy_async(&Bl[0][bk][bn0 + 8], g_w1lo + off + 8, 16);
        __pipeline_commit();
    }
    LOAD_A(0);

    for (int c = 0; c < 16; c++) {
        int s = c & 1;
        __pipeline_wait_prior(0);   // B(c) arrived
        __syncthreads();
        if (c < 15) {               // B(c+1) -> alternate stage, hidden under MMAs
            size_t off = (size_t)((c + 1) * 32 + bk) * HID_DIM + bn0;
            __pipeline_memcpy_async(&Bh[s ^ 1][bk][bn0],     g_w1hi + off,     16);
            __pipeline_memcpy_async(&Bh[s ^ 1][bk][bn0 + 8], g_w1hi + off + 8, 16);
            __pipeline_memcpy_async(&Bl[s ^ 1][bk][bn0],     g_w1lo + off,     16);
            __pipeline_memcpy_async(&Bl[s ^ 1][bk][bn0 + 8], g_w1lo + off + 8, 16);
            __pipeline_commit();
        }

        #pragma unroll
        for (int ks = 0; ks < 2; ks++) {
            // convert prefetched A floats -> hi/lo fragments (registers only)
            uint32_t ah[2][4], al[2][4];
            #pragma unroll
            for (int i = 0; i < 2; i++)
                #pragma unroll
                for (int q = 0; q < 4; q++) {
                    float2 v = areg[i * 4 + q];
                    ah[i][q] = pack_bf16_hi(v.x, v.y);
                    al[i][q] = pack_bf16_hi(bf_res(v.x), bf_res(v.y));
                }
            // prefetch A for next ks / next chunk
            {
                int nc = c, nks = ks + 1;
                if (nks == 2) { nc = c + 1; nks = 0; }
                if (nc < 16) LOAD_A(nc * 32 + nks * 16);
            }

            uint32_t base_h = bh_sh + s * STAGE_B + lm_off + (uint32_t)(ks * 16 * 136 * 2);
            uint32_t base_l = bl_sh + s * STAGE_B + lm_off + (uint32_t)(ks * 16 * 136 * 2);
            #pragma unroll
            for (int jp = 0; jp < 4; jp++) {
                uint32_t h0, h1, h2, h3, l0, l1, l2, l3;
                ldsm4t(h0, h1, h2, h3, base_h + jp * 32);   // 16 cols * 2B
                ldsm4t(l0, l1, l2, l3, base_l + jp * 32);
                #pragma unroll
                for (int i = 0; i < 2; i++) {
                    mma_bf16(acc[i][2 * jp],     ah[i], h0, h1);
                    mma_bf16(acc[i][2 * jp],     ah[i], l0, l1);
                    mma_bf16(acc[i][2 * jp],     al[i], h0, h1);
                    mma_bf16(acc[i][2 * jp + 1], ah[i], h2, h3);
                    mma_bf16(acc[i][2 * jp + 1], ah[i], l2, l3);
                    mma_bf16(acc[i][2 * jp + 1], al[i], h2, h3);
                }
            }
        }
    }

    // epilogue: c-fragment mapping -> g_h1 (padded, no bounds checks)
    #pragma unroll
    for (int i = 0; i < 2; i++) {
        int r = row0 + warp_m * 32 + i * 16 + g;
        #pragma unroll
        for (int j = 0; j < 8; j++) {
            int cb = warp_n * 64 + j * 8 + 2 * tig;
            *(float2*)&g_h1[(size_t)r * HID_DIM + cb]       = make_float2(acc[i][j][0], acc[i][j][1]);
            *(float2*)&g_h1[(size_t)(r + 8) * HID_DIM + cb] = make_float2(acc[i][j][2], acc[i][j][3]);
        }
    }
}

// ---------------- preprocessing ----------------
__global__ void k_init() {
    int i = blockIdx.x * 256 + threadIdx.x;
    if (i < N_NODES) { g_deg[i] = 0; g_cursor[i] = 0; }
}
__global__ void k_degree(const void* __restrict__ ei) {
    int e = blockIdx.x * 256 + threadIdx.x;
    if (e >= N_EDGES) return;
    int d = edge_id(ei, (size_t)N_EDGES + e);
    if ((unsigned)d < N_NODES) atomicAdd(&g_deg[d], 1);
}
__global__ void k_dinv() {
    int i = blockIdx.x * 256 + threadIdx.x;
    if (i < N_NODES) g_dinv[i] = rsqrtf((float)(g_deg[i] + 1));
}
__global__ __launch_bounds__(1024) void k_scan1() {
    __shared__ int wsum[32];
    int t = threadIdx.x, lane = t & 31, w = t >> 5;
    int idx = blockIdx.x * 1024 + t;
    int v = (idx < N_NODES) ? g_deg[idx] : 0;
    int x = v;
    #pragma unroll
    for (int d = 1; d < 32; d <<= 1) {
        int y = __shfl_up_sync(0xffffffffu, x, d);
        if (lane >= d) x += y;
    }
    if (lane == 31) wsum[w] = x;
    __syncthreads();
    if (w == 0) {
        int s = wsum[lane];
        #pragma unroll
        for (int d = 1; d < 32; d <<= 1) {
            int y = __shfl_up_sync(0xffffffffu, s, d);
            if (lane >= d) s += y;
        }
        wsum[lane] = s;
    }
    __syncthreads();
    int woff = w ? wsum[w - 1] : 0;
    if (idx < N_NODES) g_rowptr[idx] = woff + x - v;
    if (t == 1023) g_bsum[blockIdx.x] = wsum[31];
}
__global__ void k_scan2(int nb) {
    __shared__ int ws[4];
    __shared__ int tot;
    int t = threadIdx.x, lane = t & 31, w = t >> 5;
    int v = (t < nb) ? g_bsum[t] : 0;
    int x = v;
    #pragma unroll
    for (int d = 1; d < 32; d <<= 1) {
        int y = __shfl_up_sync(0xffffffffu, x, d);
        if (lane >= d) x += y;
    }
    if (lane == 31) ws[w] = x;
    __syncthreads();
    if (t == 0) {
        int s = 0;
        #pragma unroll
        for (int i = 0; i < 4; i++) { int tv = ws[i]; ws[i] = s; s += tv; }
        tot = s;
    }
    __syncthreads();
    if (t < nb) g_bsum[t] = ws[w] + x - v;
    if (t == 0) g_rowptr[N_NODES] = tot;
}
__global__ void k_scan3() {
    int idx = blockIdx.x * 256 + threadIdx.x;
    if (idx < N_NODES) g_rowptr[idx] += g_bsum[idx >> 10];
}
__global__ void k_scatter(const void* __restrict__ ei) {
    int e = blockIdx.x * 256 + threadIdx.x;
    if (e >= N_EDGES) return;
    int s = edge_id(ei, e);
    int d = edge_id(ei, (size_t)N_EDGES + e);
    if ((unsigned)s >= N_NODES || (unsigned)d >= N_NODES) return;
    int p = g_rowptr[d] + atomicAdd(&g_cursor[d], 1);
    g_csr_src[p] = s;
}

// ---------------- aggregation 1: relu(agg + b1), writes bf16 hi/lo ----------------
__global__ __launch_bounds__(256) void k_agg1(const float* __restrict__ b1) {
    int node = blockIdx.x * 8 + (threadIdx.x >> 5);
    if (node >= N_NODES) return;
    int lane = threadIdx.x & 31;
    const float4* h = (const float4*)g_h1;

    float dn = g_dinv[node];
    float4 acc = h[(size_t)node * 32 + lane];
    acc.x *= dn; acc.y *= dn; acc.z *= dn; acc.w *= dn;

    int p0 = g_rowptr[node], p1 = g_rowptr[node + 1];
    for (int p = p0; p < p1; p++) {
        int s  = g_csr_src[p];
        float w = g_dinv[s];
        float4 v = h[(size_t)s * 32 + lane];
        acc.x += w * v.x; acc.y += w * v.y; acc.z += w * v.z; acc.w += w * v.w;
    }
    float4 bb = ((const float4*)b1)[lane];
    float4 o;
    o.x = fmaxf(fmaf(dn, acc.x, bb.x), 0.f);
    o.y = fmaxf(fmaf(dn, acc.y, bb.y), 0.f);
    o.z = fmaxf(fmaf(dn, acc.z, bb.z), 0.f);
    o.w = fmaxf(fmaf(dn, acc.w, bb.w), 0.f);

    uint2 hw = make_uint2(pack_bf16_hi(o.x, o.y), pack_bf16_hi(o.z, o.w));
    uint2 lw = make_uint2(pack_bf16_hi(bf_res(o.x), bf_res(o.y)),
                          pack_bf16_hi(bf_res(o.z), bf_res(o.w)));
    *(uint2*)&g_a1hi[(size_t)node * HID_DIM + lane * 4] = hw;
    *(uint2*)&g_a1lo[(size_t)node * HID_DIM + lane * 4] = lw;
}

// ---------------- GEMM2: g_h2p = a1 @ W2, wmma bf16 3-term ----------------
__global__ __launch_bounds__(256, 2) void k_gemm2_mma() {
    __shared__ __nv_bfloat16 Ah[128][40];
    __shared__ __nv_bfloat16 Al[128][40];
    __shared__ __nv_bfloat16 Bh[32][72];
    __shared__ __nv_bfloat16 Bl[32][72];

    int t = threadIdx.x;
    int wid = t >> 5;           // rows wid*16
    int row0 = blockIdx.x * 128;

    wmma::fragment<wmma::accumulator, 16, 16, 16, float> acc[4];
    #pragma unroll
    for (int j = 0; j < 4; j++) wmma::fill_fragment(acc[j], 0.f);

    int arow = t >> 1, aseg = t & 1;
    int bk = t >> 3, bn0 = (t & 7) << 3;

    for (int c = 0; c < 4; c++) {
        {
            size_t aoff = (size_t)(row0 + arow) * HID_DIM + c * 32 + aseg * 16;
            __pipeline_memcpy_async(&Ah[arow][aseg * 16],     g_a1hi + aoff,     16);
            __pipeline_memcpy_async(&Ah[arow][aseg * 16 + 8], g_a1hi + aoff + 8, 16);
            __pipeline_memcpy_async(&Al[arow][aseg * 16],     g_a1lo + aoff,     16);
            __pipeline_memcpy_async(&Al[arow][aseg * 16 + 8], g_a1lo + aoff + 8, 16);
            size_t boff = (size_t)(c * 32 + bk) * OUT_PAD + bn0;
            __pipeline_memcpy_async(&Bh[bk][bn0], g_w2hi + boff, 16);
            __pipeline_memcpy_async(&Bl[bk][bn0], g_w2lo + boff, 16);
            __pipeline_commit();
        }
        __pipeline_wait_prior(0);
        __syncthreads();

        #pragma unroll
        for (int ks = 0; ks < 2; ks++) {
            wmma::fragment<wmma::matrix_a, 16, 16, 16, __nv_bfloat16, wmma::row_major> ah, al;
            wmma::load_matrix_sync(ah, &Ah[wid * 16][ks * 16], 40);
            wmma::load_matrix_sync(al, &Al[wid * 16][ks * 16], 40);
            #pragma unroll
            for (int j = 0; j < 4; j++) {
                wmma::fragment<wmma::matrix_b, 16, 16, 16, __nv_bfloat16, wmma::row_major> bh, bl;
                wmma::load_matrix_sync(bh, &Bh[ks * 16][j * 16], 72);
                wmma::load_matrix_sync(bl, &Bl[ks * 16][j * 16], 72);
                wmma::mma_sync(acc[j], ah, bh, acc[j]);
                wmma::mma_sync(acc[j], ah, bl, acc[j]);
                wmma::mma_sync(acc[j], al, bh, acc[j]);
            }
        }
        __syncthreads();
    }

    #pragma unroll
    for (int j = 0; j < 4; j++) {
        size_t off = (size_t)(row0 + wid * 16) * OUT_PAD + j * 16;
        wmma::store_matrix_sync(&g_h2p[off], acc[j], OUT_PAD, wmma::mem_row_major);
    }
}

// ---------------- aggregation 2 + bias + log_softmax ----------------
__global__ __launch_bounds__(256) void k_agg2(const float* __restrict__ b2,
                                              float* __restrict__ out) {
    int node = blockIdx.x * 8 + (threadIdx.x >> 5);
    if (node >= N_NODES) return;
    int lane = threadIdx.x & 31;

    float dn = g_dinv[node];
    float acc0, acc1 = 0.f;
    {
        size_t b = (size_t)node * OUT_PAD;
        acc0 = dn * g_h2p[b + lane];
        if (lane < 8) acc1 = dn * g_h2p[b + 32 + lane];
    }
    int p0 = g_rowptr[node], p1 = g_rowptr[node + 1];
    for (int p = p0; p < p1; p++) {
        int s  = g_csr_src[p];
        float w = g_dinv[s];
        size_t b = (size_t)s * OUT_PAD;
        acc0 += w * g_h2p[b + lane];
        if (lane < 8) acc1 += w * g_h2p[b + 32 + lane];
    }
    acc0 = fmaf(dn, acc0, b2[lane]);
    if (lane < 8) acc1 = fmaf(dn, acc1, b2[32 + lane]);

    float m = acc0;
    if (lane < 8) m = fmaxf(m, acc1);
    #pragma unroll
    for (int o = 16; o; o >>= 1) m = fmaxf(m, __shfl_xor_sync(0xffffffffu, m, o));
    float s = __expf(acc0 - m) + ((lane < 8) ? __expf(acc1 - m) : 0.f);
    #pragma unroll
    for (int o = 16; o; o >>= 1) s += __shfl_xor_sync(0xffffffffu, s, o);
    float ls = __logf(s);

    out[(size_t)node * OUT_DIM + lane] = acc0 - m - ls;
    if (lane < 8) out[(size_t)node * OUT_DIM + 32 + lane] = acc1 - m - ls;
}

// ---------------- launch ----------------
extern "C" void kernel_launch(void* const* d_in, const int* in_sizes, int n_in,
                              void* d_out, int out_size) {
    const float* x  = (const float*)d_in[0];
    const void*  ei = d_in[1];
    const float* W1 = (const float*)d_in[2];
    const float* b1 = (const float*)d_in[3];
    const float* W2 = (const float*)d_in[4];
    const float* b2 = (const float*)d_in[5];
    float*       out = (float*)d_out;

    const int TB = 256;
    int nb_nodes = (N_NODES + TB - 1) / TB;
    int nb_edges = (N_EDGES + TB - 1) / TB;
    int nb_scan  = (N_NODES + 1023) / 1024;   // 98

    // Order keeps k_gemm1_mma at ncu's captured slot (launch index 3).
    k_detect<<<1, 1>>>(ei);                          // 0
    k_wsplit<<<(K_PAD * HID_DIM) / TB, TB>>>(W1);    // 1
    k_w2split<<<(HID_DIM * OUT_PAD) / TB, TB>>>(W2); // 2
    k_gemm1_mma<<<N_PAD / 128, 256>>>(x);            // 3 <- profiled
    k_init<<<nb_nodes, TB>>>();                      // 4
    k_degree<<<nb_edges, TB>>>(ei);                  // 5
    k_dinv<<<nb_nodes, TB>>>();                      // 6
    k_scan1<<<nb_scan, 1024>>>();
    k_scan2<<<1, 128>>>(nb_scan);
    k_scan3<<<nb_nodes, TB>>>();
    k_scatter<<<nb_edges, TB>>>(ei);
    k_agg1<<<(N_NODES + 7) / 8, 256>>>(b1);
    k_gemm2_mma<<<N_PAD / 128, 256>>>();
    k_agg2<<<(N_NODES + 7) / 8, 256>>>(b2, out);
}